// round 5
// baseline (speedup 1.0000x reference)
#include <cuda_runtime.h>
#include <cstdint>

#define THREADS 256
#define ROWS    128     // batch rows per block
#define DM      64
#define SEQ     9
#define NOUT    300
#define A_LD    132     // padded leading dim -> conflict-free frag LDS
#define B_LD    132

__device__ __forceinline__ unsigned f2tf(float f) {
    unsigned u;
    asm("cvt.rna.tf32.f32 %0, %1;" : "=r"(u) : "f"(f));
    return u;
}
__device__ __forceinline__ float tfbits(float f) { return __uint_as_float(f2tf(f)); }

__device__ __forceinline__ float sigf(float v) {
    return __fdividef(1.0f, 1.0f + __expf(-v));
}

__device__ __forceinline__ void mma8(float* c,
                                     unsigned a0, unsigned a1, unsigned a2, unsigned a3,
                                     unsigned b0, unsigned b1) {
    asm volatile(
        "mma.sync.aligned.m16n8k8.row.col.f32.tf32.tf32.f32 "
        "{%0,%1,%2,%3}, {%4,%5,%6,%7}, {%8,%9}, {%0,%1,%2,%3};"
        : "+f"(c[0]), "+f"(c[1]), "+f"(c[2]), "+f"(c[3])
        : "r"(a0), "r"(a1), "r"(a2), "r"(a3), "r"(b0), "r"(b1));
}

__global__ void __launch_bounds__(THREADS, 2) carnn_kernel(
    const int*   __restrict__ acts,   // [B, 9] int32
    const float* __restrict__ emb,    // [301, 64]
    const float* __restrict__ Mw,     // [50, 64, 64]
    const float* __restrict__ Mb,     // [50, 64]
    const float* __restrict__ Ww,     // [56, 64, 64]
    const float* __restrict__ Wb,     // [56, 64]
    const float* __restrict__ outw,   // [300, 64]
    const float* __restrict__ outb,   // [300]
    float*       __restrict__ out)    // [B, 300]
{
    extern __shared__ float smem[];
    float* sA    = smem;                 // [128][A_LD]: cols 0..63 = X_s, 64..127 = H (tf32 bits)
    float* sB    = sA + ROWS * A_LD;     // [64][B_LD]: n-major weights (tf32 bits)
    float* sBias = sB + DM * B_LD;       // [64]

    const int tid  = threadIdx.x;
    const int lane = tid & 31;
    const int warp = tid >> 5;
    const int g    = lane >> 2;          // groupID
    const int tg   = lane & 3;           // threadID_in_group
    const int row0 = warp * 16 + g;      // warp's m16 slice
    const int row1 = row0 + 8;
    const long base = (long)blockIdx.x * ROWS;

    const int grow  = tid >> 1;          // gather: 2 threads per batch row
    const int ghalf = tid & 1;

    // ================= RNN: 9 steps =================
    for (int s = 0; s < SEQ; s++) {
        __syncthreads();  // guard prior step's smem reads before overwrite

        // ---- gather X_s -> sA[:, 0:64] (tf32)
        {
            const int a = acts[(base + grow) * SEQ + s];
            const float4* er  = reinterpret_cast<const float4*>(emb + a * DM) + ghalf * 8;
            float*        dst = sA + grow * A_LD + ghalf * 32;
            #pragma unroll
            for (int j = 0; j < 8; j++) {
                float4 v = er[j];
                float4 w;
                w.x = tfbits(v.x); w.y = tfbits(v.y);
                w.z = tfbits(v.z); w.w = tfbits(v.w);
                *reinterpret_cast<float4*>(dst + j * 4) = w;
            }
        }
        // ---- weights: sB[n][0..63] = Mw_s[n][:], sB[n][64..127] = Ww_s[n][:]
        {
            const float* Mws = Mw + s * DM * DM;
            const float* Wws = Ww + s * DM * DM;
            #pragma unroll
            for (int it = 0; it < (DM * DM) / THREADS; it++) {
                int idx = it * THREADS + tid;
                int n = idx >> 6, k = idx & 63;
                sB[n * B_LD + k]      = tfbits(Mws[idx]);
                sB[n * B_LD + 64 + k] = tfbits(Wws[idx]);
            }
            if (tid < DM) sBias[tid] = Mb[s * DM + tid] + Wb[s * DM + tid];
        }
        __syncthreads();

        // ---- [X|H] @ [Mw;Ww]^T : M=16(warp), N=64, K=128 (64 at s=0 since h0=0)
        float acc[8][4];
        #pragma unroll
        for (int nn = 0; nn < 8; nn++)
            acc[nn][0] = acc[nn][1] = acc[nn][2] = acc[nn][3] = 0.0f;

        const int Kc = (s == 0) ? 8 : 16;
        #pragma unroll 4
        for (int kk = 0; kk < Kc; kk++) {
            const int k0 = kk * 8;
            unsigned a0 = __float_as_uint(sA[row0 * A_LD + k0 + tg]);
            unsigned a1 = __float_as_uint(sA[row1 * A_LD + k0 + tg]);
            unsigned a2 = __float_as_uint(sA[row0 * A_LD + k0 + tg + 4]);
            unsigned a3 = __float_as_uint(sA[row1 * A_LD + k0 + tg + 4]);
            #pragma unroll
            for (int nn = 0; nn < 8; nn++) {
                const int n = nn * 8 + g;
                unsigned b0 = __float_as_uint(sB[n * B_LD + k0 + tg]);
                unsigned b1 = __float_as_uint(sB[n * B_LD + k0 + tg + 4]);
                mma8(acc[nn], a0, a1, a2, a3, b0, b1);
            }
        }

        // ---- bias + sigmoid -> H (tf32) into sA[:, 64:128]
        #pragma unroll
        for (int nn = 0; nn < 8; nn++) {
            const int c = nn * 8 + 2 * tg;
            const float bb0 = sBias[c], bb1 = sBias[c + 1];
            float2 p0, p1;
            p0.x = tfbits(sigf(acc[nn][0] + bb0));
            p0.y = tfbits(sigf(acc[nn][1] + bb1));
            p1.x = tfbits(sigf(acc[nn][2] + bb0));
            p1.y = tfbits(sigf(acc[nn][3] + bb1));
            *reinterpret_cast<float2*>(sA + row0 * A_LD + 64 + c) = p0;
            *reinterpret_cast<float2*>(sA + row1 * A_LD + 64 + c) = p1;
        }
    }

    // ================= Output GEMM: H[128,64] @ out_w^T + out_b =================
    for (int nc = 0; nc < 5; nc++) {   // 5 chunks of 64 cols (300 padded to 320)
        __syncthreads();
        #pragma unroll
        for (int it = 0; it < (DM * DM) / THREADS; it++) {
            int idx = it * THREADS + tid;
            int n = idx >> 6, k = idx & 63;
            int gn = nc * DM + n;
            sB[n * B_LD + k] = (gn < NOUT) ? tfbits(outw[gn * DM + k]) : 0.0f;
        }
        if (tid < DM) {
            int gn = nc * DM + tid;
            sBias[tid] = (gn < NOUT) ? outb[gn] : 0.0f;
        }
        __syncthreads();

        float acc[8][4];
        #pragma unroll
        for (int nn = 0; nn < 8; nn++)
            acc[nn][0] = acc[nn][1] = acc[nn][2] = acc[nn][3] = 0.0f;

        #pragma unroll
        for (int kk = 0; kk < 8; kk++) {
            const int ka = 64 + kk * 8;   // A = H lives in cols 64..127
            const int kb = kk * 8;
            unsigned a0 = __float_as_uint(sA[row0 * A_LD + ka + tg]);
            unsigned a1 = __float_as_uint(sA[row1 * A_LD + ka + tg]);
            unsigned a2 = __float_as_uint(sA[row0 * A_LD + ka + tg + 4]);
            unsigned a3 = __float_as_uint(sA[row1 * A_LD + ka + tg + 4]);
            #pragma unroll
            for (int nn = 0; nn < 8; nn++) {
                const int n = nn * 8 + g;
                unsigned b0 = __float_as_uint(sB[n * B_LD + kb + tg]);
                unsigned b1 = __float_as_uint(sB[n * B_LD + kb + tg + 4]);
                mma8(acc[nn], a0, a1, a2, a3, b0, b1);
            }
        }

        const long r0 = base + row0, r1 = base + row1;
        #pragma unroll
        for (int nn = 0; nn < 8; nn++) {
            const int c  = nn * 8 + 2 * tg;
            const int gc = nc * DM + c;
            if (gc < NOUT) {   // NOUT even -> pair validity uniform; addr 8B-aligned
                const float bb0 = sBias[c], bb1 = sBias[c + 1];
                float2 p0, p1;
                p0.x = acc[nn][0] + bb0; p0.y = acc[nn][1] + bb1;
                p1.x = acc[nn][2] + bb0; p1.y = acc[nn][3] + bb1;
                *reinterpret_cast<float2*>(out + r0 * NOUT + gc) = p0;
                *reinterpret_cast<float2*>(out + r1 * NOUT + gc) = p1;
            }
        }
    }
}

extern "C" void kernel_launch(void* const* d_in, const int* in_sizes, int n_in,
                              void* d_out, int out_size) {
    const int*   acts = (const int*)  d_in[0];
    const float* emb  = (const float*)d_in[1];
    const float* Mw   = (const float*)d_in[2];
    const float* Mb   = (const float*)d_in[3];
    const float* Ww   = (const float*)d_in[4];
    const float* Wb   = (const float*)d_in[5];
    const float* outw = (const float*)d_in[6];
    const float* outb = (const float*)d_in[7];
    float* out = (float*)d_out;

    const int smem = (ROWS * A_LD + DM * B_LD + DM) * (int)sizeof(float);  // ~101.6 KB
    cudaFuncSetAttribute(carnn_kernel, cudaFuncAttributeMaxDynamicSharedMemorySize, smem);

    const int B = in_sizes[0] / SEQ;   // 65536
    carnn_kernel<<<B / ROWS, THREADS, smem>>>(acts, emb, Mw, Mb, Ww, Wb, outw, outb, out);
}

// round 6
// speedup vs baseline: 1.1604x; 1.1604x over previous
#include <cuda_runtime.h>
#include <cstdint>

#define THREADS 128
#define ROWS    128     // batch rows per block
#define DM      64
#define SEQ     9
#define NOUT    300
#define A_LD    132     // padded leading dim -> conflict-free frag LDS
#define B_LD    132

__device__ __forceinline__ unsigned f2tf(float f) {
    unsigned u;
    asm("cvt.rna.tf32.f32 %0, %1;" : "=r"(u) : "f"(f));
    return u;
}
__device__ __forceinline__ float tfbits(float f) { return __uint_as_float(f2tf(f)); }

__device__ __forceinline__ float sigf(float v) {
    return __fdividef(1.0f, 1.0f + __expf(-v));
}

__device__ __forceinline__ void mma8(float* c,
                                     unsigned a0, unsigned a1, unsigned a2, unsigned a3,
                                     unsigned b0, unsigned b1) {
    asm volatile(
        "mma.sync.aligned.m16n8k8.row.col.f32.tf32.tf32.f32 "
        "{%0,%1,%2,%3}, {%4,%5,%6,%7}, {%8,%9}, {%0,%1,%2,%3};"
        : "+f"(c[0]), "+f"(c[1]), "+f"(c[2]), "+f"(c[3])
        : "r"(a0), "r"(a1), "r"(a2), "r"(a3), "r"(b0), "r"(b1));
}

__global__ void __launch_bounds__(THREADS) carnn_kernel(
    const int*   __restrict__ acts,   // [B, 9] int32
    const float* __restrict__ emb,    // [301, 64]
    const float* __restrict__ Mw,     // [50, 64, 64]
    const float* __restrict__ Mb,     // [50, 64]
    const float* __restrict__ Ww,     // [56, 64, 64]
    const float* __restrict__ Wb,     // [56, 64]
    const float* __restrict__ outw,   // [300, 64]
    const float* __restrict__ outb,   // [300]
    float*       __restrict__ out)    // [B, 300]
{
    extern __shared__ float smem[];
    float* sA    = smem;                 // [128][A_LD]: cols 0..63 = X_s, 64..127 = H (tf32 bits)
    float* sB    = sA + ROWS * A_LD;     // [64][B_LD]: n-major weights (tf32 bits)
    float* sBias = sB + DM * B_LD;       // [64]

    const int tid  = threadIdx.x;
    const int lane = tid & 31;
    const int warp = tid >> 5;
    const int g    = lane >> 2;          // groupID
    const int tg   = lane & 3;           // threadID_in_group
    // warp tile: M=32 rows, N=64 cols (two m16 slices share every B fragment)
    const int rA = warp * 32 + g;
    const int rB = rA + 8;
    const int rC = rA + 16;
    const int rD = rA + 24;
    const long base = (long)blockIdx.x * ROWS;

    // hoist this row's action ids (thread t <-> batch row t)
    int myAct[SEQ];
    {
        const int* ap = acts + (base + tid) * SEQ;
        #pragma unroll
        for (int s = 0; s < SEQ; s++) myAct[s] = ap[s];
    }

    // ================= RNN: 9 steps =================
    for (int s = 0; s < SEQ; s++) {
        __syncthreads();  // prior step's smem reads done before overwrite

        // ---- gather X_s -> sA[tid][0:64] (tf32), one thread per row
        {
            const float4* er  = reinterpret_cast<const float4*>(emb + myAct[s] * DM);
            float*        dst = sA + tid * A_LD;
            #pragma unroll
            for (int j = 0; j < 16; j++) {
                float4 v = er[j];
                float4 w;
                w.x = tfbits(v.x); w.y = tfbits(v.y);
                w.z = tfbits(v.z); w.w = tfbits(v.w);
                *reinterpret_cast<float4*>(dst + j * 4) = w;
            }
        }
        // ---- weights: sB[n][0..63] = Mw_s[n][:], sB[n][64..127] = Ww_s[n][:]
        {
            const float4* Mws = reinterpret_cast<const float4*>(Mw + s * DM * DM);
            const float4* Wws = reinterpret_cast<const float4*>(Ww + s * DM * DM);
            #pragma unroll
            for (int it = 0; it < 8; it++) {          // 1024 float4s / 128 threads
                int e  = it * THREADS + tid;
                int n  = e >> 4, k4 = e & 15;
                float4 m = Mws[e], w = Wws[e], tm, tw;
                tm.x = tfbits(m.x); tm.y = tfbits(m.y); tm.z = tfbits(m.z); tm.w = tfbits(m.w);
                tw.x = tfbits(w.x); tw.y = tfbits(w.y); tw.z = tfbits(w.z); tw.w = tfbits(w.w);
                *reinterpret_cast<float4*>(sB + n * B_LD + k4 * 4)      = tm;
                *reinterpret_cast<float4*>(sB + n * B_LD + 64 + k4 * 4) = tw;
            }
            if (tid < DM) sBias[tid] = Mb[s * DM + tid] + Wb[s * DM + tid];
        }
        __syncthreads();

        // ---- [X|H] @ [Mw;Ww]^T : per warp M=32, N=64, K=128 (K=64 at s=0, h0=0)
        float c0[8][4], c1[8][4];
        #pragma unroll
        for (int nn = 0; nn < 8; nn++) {
            c0[nn][0] = c0[nn][1] = c0[nn][2] = c0[nn][3] = 0.0f;
            c1[nn][0] = c1[nn][1] = c1[nn][2] = c1[nn][3] = 0.0f;
        }

        const int Kc = (s == 0) ? 8 : 16;
        #pragma unroll 4
        for (int kk = 0; kk < Kc; kk++) {
            const int k0 = kk * 8;
            const float* pa = sA + k0 + tg;
            unsigned a0 = __float_as_uint(pa[rA * A_LD]);
            unsigned a1 = __float_as_uint(pa[rB * A_LD]);
            unsigned a2 = __float_as_uint(pa[rA * A_LD + 4]);
            unsigned a3 = __float_as_uint(pa[rB * A_LD + 4]);
            unsigned a4 = __float_as_uint(pa[rC * A_LD]);
            unsigned a5 = __float_as_uint(pa[rD * A_LD]);
            unsigned a6 = __float_as_uint(pa[rC * A_LD + 4]);
            unsigned a7 = __float_as_uint(pa[rD * A_LD + 4]);
            #pragma unroll
            for (int nn = 0; nn < 8; nn++) {
                const int n = nn * 8 + g;
                unsigned b0 = __float_as_uint(sB[n * B_LD + k0 + tg]);
                unsigned b1 = __float_as_uint(sB[n * B_LD + k0 + tg + 4]);
                mma8(c0[nn], a0, a1, a2, a3, b0, b1);
                mma8(c1[nn], a4, a5, a6, a7, b0, b1);
            }
        }

        // ---- bias + sigmoid -> H (tf32) into sA[:, 64:128]  (warp-private rows)
        #pragma unroll
        for (int nn = 0; nn < 8; nn++) {
            const int c = nn * 8 + 2 * tg;
            const float bb0 = sBias[c], bb1 = sBias[c + 1];
            float2 p;
            p.x = tfbits(sigf(c0[nn][0] + bb0));
            p.y = tfbits(sigf(c0[nn][1] + bb1));
            *reinterpret_cast<float2*>(sA + rA * A_LD + 64 + c) = p;
            p.x = tfbits(sigf(c0[nn][2] + bb0));
            p.y = tfbits(sigf(c0[nn][3] + bb1));
            *reinterpret_cast<float2*>(sA + rB * A_LD + 64 + c) = p;
            p.x = tfbits(sigf(c1[nn][0] + bb0));
            p.y = tfbits(sigf(c1[nn][1] + bb1));
            *reinterpret_cast<float2*>(sA + rC * A_LD + 64 + c) = p;
            p.x = tfbits(sigf(c1[nn][2] + bb0));
            p.y = tfbits(sigf(c1[nn][3] + bb1));
            *reinterpret_cast<float2*>(sA + rD * A_LD + 64 + c) = p;
        }
    }

    // ================= Output GEMM: H[128,64] @ out_w^T + out_b =================
    for (int nc = 0; nc < 5; nc++) {   // 5 chunks of 64 cols (300 padded to 320)
        __syncthreads();
        #pragma unroll
        for (int it = 0; it < 8; it++) {
            int e  = it * THREADS + tid;
            int n  = e >> 4, k4 = e & 15;
            int gn = nc * DM + n;
            float4 tw;
            if (gn < NOUT) {
                float4 w = reinterpret_cast<const float4*>(outw + gn * DM)[k4];
                tw.x = tfbits(w.x); tw.y = tfbits(w.y); tw.z = tfbits(w.z); tw.w = tfbits(w.w);
            } else {
                tw.x = tw.y = tw.z = tw.w = 0.0f;
            }
            *reinterpret_cast<float4*>(sB + n * B_LD + k4 * 4) = tw;
        }
        if (tid < DM) {
            int gn = nc * DM + tid;
            sBias[tid] = (gn < NOUT) ? outb[gn] : 0.0f;
        }
        __syncthreads();

        float c0[8][4], c1[8][4];
        #pragma unroll
        for (int nn = 0; nn < 8; nn++) {
            c0[nn][0] = c0[nn][1] = c0[nn][2] = c0[nn][3] = 0.0f;
            c1[nn][0] = c1[nn][1] = c1[nn][2] = c1[nn][3] = 0.0f;
        }

        #pragma unroll
        for (int kk = 0; kk < 8; kk++) {
            const int ka = 64 + kk * 8;   // A = H lives in cols 64..127
            const int kb = kk * 8;
            const float* pa = sA + ka + tg;
            unsigned a0 = __float_as_uint(pa[rA * A_LD]);
            unsigned a1 = __float_as_uint(pa[rB * A_LD]);
            unsigned a2 = __float_as_uint(pa[rA * A_LD + 4]);
            unsigned a3 = __float_as_uint(pa[rB * A_LD + 4]);
            unsigned a4 = __float_as_uint(pa[rC * A_LD]);
            unsigned a5 = __float_as_uint(pa[rD * A_LD]);
            unsigned a6 = __float_as_uint(pa[rC * A_LD + 4]);
            unsigned a7 = __float_as_uint(pa[rD * A_LD + 4]);
            #pragma unroll
            for (int nn = 0; nn < 8; nn++) {
                const int n = nn * 8 + g;
                unsigned b0 = __float_as_uint(sB[n * B_LD + kb + tg]);
                unsigned b1 = __float_as_uint(sB[n * B_LD + kb + tg + 4]);
                mma8(c0[nn], a0, a1, a2, a3, b0, b1);
                mma8(c1[nn], a4, a5, a6, a7, b0, b1);
            }
        }

        #pragma unroll
        for (int nn = 0; nn < 8; nn++) {
            const int c  = nn * 8 + 2 * tg;
            const int gc = nc * DM + c;
            if (gc < NOUT) {   // NOUT even -> pair validity uniform; addr 8B-aligned
                const float bb0 = sBias[c], bb1 = sBias[c + 1];
                float2 p;
                p.x = c0[nn][0] + bb0; p.y = c0[nn][1] + bb1;
                *reinterpret_cast<float2*>(out + (base + rA) * NOUT + gc) = p;
                p.x = c0[nn][2] + bb0; p.y = c0[nn][3] + bb1;
                *reinterpret_cast<float2*>(out + (base + rB) * NOUT + gc) = p;
                p.x = c1[nn][0] + bb0; p.y = c1[nn][1] + bb1;
                *reinterpret_cast<float2*>(out + (base + rC) * NOUT + gc) = p;
                p.x = c1[nn][2] + bb0; p.y = c1[nn][3] + bb1;
                *reinterpret_cast<float2*>(out + (base + rD) * NOUT + gc) = p;
            }
        }
    }
}

extern "C" void kernel_launch(void* const* d_in, const int* in_sizes, int n_in,
                              void* d_out, int out_size) {
    const int*   acts = (const int*)  d_in[0];
    const float* emb  = (const float*)d_in[1];
    const float* Mw   = (const float*)d_in[2];
    const float* Mb   = (const float*)d_in[3];
    const float* Ww   = (const float*)d_in[4];
    const float* Wb   = (const float*)d_in[5];
    const float* outw = (const float*)d_in[6];
    const float* outb = (const float*)d_in[7];
    float* out = (float*)d_out;

    const int smem = (ROWS * A_LD + DM * B_LD + DM) * (int)sizeof(float);  // ~101.6 KB
    cudaFuncSetAttribute(carnn_kernel, cudaFuncAttributeMaxDynamicSharedMemorySize, smem);

    const int B = in_sizes[0] / SEQ;   // 65536
    carnn_kernel<<<B / ROWS, THREADS, smem>>>(acts, emb, Mw, Mb, Ww, Wb, outw, outb, out);
}

// round 7
// speedup vs baseline: 1.6535x; 1.4249x over previous
#include <cuda_runtime.h>
#include <cuda_fp16.h>
#include <cstdint>

#define THREADS 128
#define ROWS    128     // batch rows per block
#define DM      64
#define SEQ     9
#define NOUT    300
#define A_LDH   136     // leading dim in halves -> conflict-free frag LDS
#define B_LDH   136

__device__ __forceinline__ unsigned pack2(float a, float b) {
    __half2 h = __floats2half2_rn(a, b);
    return *reinterpret_cast<unsigned*>(&h);
}

__device__ __forceinline__ float sigf(float v) {
    return __fdividef(1.0f, 1.0f + __expf(-v));
}

__device__ __forceinline__ void mma16(float* c,
                                      unsigned a0, unsigned a1, unsigned a2, unsigned a3,
                                      unsigned b0, unsigned b1) {
    asm volatile(
        "mma.sync.aligned.m16n8k16.row.col.f32.f16.f16.f32 "
        "{%0,%1,%2,%3}, {%4,%5,%6,%7}, {%8,%9}, {%0,%1,%2,%3};"
        : "+f"(c[0]), "+f"(c[1]), "+f"(c[2]), "+f"(c[3])
        : "r"(a0), "r"(a1), "r"(a2), "r"(a3), "r"(b0), "r"(b1));
}

__global__ void __launch_bounds__(THREADS, 4) carnn_kernel(
    const int*   __restrict__ acts,   // [B, 9] int32
    const float* __restrict__ emb,    // [301, 64]
    const float* __restrict__ Mw,     // [50, 64, 64]
    const float* __restrict__ Mb,     // [50, 64]
    const float* __restrict__ Ww,     // [56, 64, 64]
    const float* __restrict__ Wb,     // [56, 64]
    const float* __restrict__ outw,   // [300, 64]
    const float* __restrict__ outb,   // [300]
    float*       __restrict__ out)    // [B, 300]
{
    extern __shared__ __align__(16) char smem_raw[];
    __half* sA    = reinterpret_cast<__half*>(smem_raw);          // [128][A_LDH]: 0..63 X, 64..127 H
    __half* sB    = sA + ROWS * A_LDH;                            // [64][B_LDH]: n-major weights
    float*  sBias = reinterpret_cast<float*>(sB + DM * B_LDH);    // [64]

    const int tid  = threadIdx.x;
    const int lane = tid & 31;
    const int warp = tid >> 5;
    const int g    = lane >> 2;          // groupID
    const int tg   = lane & 3;           // threadID_in_group
    // warp tile: M=32 rows x N=64
    const int rA = warp * 32 + g;
    const int rB = rA + 8;
    const int rC = rA + 16;
    const int rD = rA + 24;
    const long base = (long)blockIdx.x * ROWS;

    // hoist this row's action ids (thread t <-> batch row t)
    int myAct[SEQ];
    {
        const int* ap = acts + (base + tid) * SEQ;
        #pragma unroll
        for (int s = 0; s < SEQ; s++) myAct[s] = ap[s];
    }

    // ================= RNN: 9 steps =================
    for (int s = 0; s < SEQ; s++) {
        __syncthreads();  // prior step's sB/X reads done before overwrite

        // ---- gather X_s -> sA[tid][0:64] (fp16), one thread per row
        {
            const float4* er  = reinterpret_cast<const float4*>(emb + myAct[s] * DM);
            uint4*        dst = reinterpret_cast<uint4*>(sA + tid * A_LDH);  // 272B offset, 16B aligned
            #pragma unroll
            for (int j = 0; j < 16; j += 2) {
                float4 v0 = er[j], v1 = er[j + 1];
                uint4 w;
                w.x = pack2(v0.x, v0.y); w.y = pack2(v0.z, v0.w);
                w.z = pack2(v1.x, v1.y); w.w = pack2(v1.z, v1.w);
                dst[j >> 1] = w;
            }
        }
        // ---- weights: sB[n][0..63] = Mw_s[n][:], sB[n][64..127] = Ww_s[n][:]
        {
            const float4* Mws = reinterpret_cast<const float4*>(Mw + s * DM * DM);
            const float4* Wws = reinterpret_cast<const float4*>(Ww + s * DM * DM);
            #pragma unroll
            for (int it = 0; it < 8; it++) {          // 1024 float4s / 128 threads
                int e  = it * THREADS + tid;
                int n  = e >> 4, k4 = e & 15;
                float4 m = Mws[e], w = Wws[e];
                uint2 tm = make_uint2(pack2(m.x, m.y), pack2(m.z, m.w));
                uint2 tw = make_uint2(pack2(w.x, w.y), pack2(w.z, w.w));
                *reinterpret_cast<uint2*>(sB + n * B_LDH + k4 * 4)      = tm;
                *reinterpret_cast<uint2*>(sB + n * B_LDH + 64 + k4 * 4) = tw;
            }
            if (tid < DM) sBias[tid] = Mb[s * DM + tid] + Wb[s * DM + tid];
        }
        __syncthreads();

        // ---- [X|H] @ [Mw;Ww]^T : per warp M=32, N=64, K=128 (K=64 at s=0, h0=0)
        float c0[8][4], c1[8][4];
        #pragma unroll
        for (int nn = 0; nn < 8; nn++) {
            c0[nn][0] = c0[nn][1] = c0[nn][2] = c0[nn][3] = 0.0f;
            c1[nn][0] = c1[nn][1] = c1[nn][2] = c1[nn][3] = 0.0f;
        }

        const int Kc = (s == 0) ? 4 : 8;     // chunks of K=16
        #pragma unroll 4
        for (int kk = 0; kk < Kc; kk++) {
            const int k0 = kk * 16;
            const __half* pa = sA + k0 + 2 * tg;
            unsigned a0 = *reinterpret_cast<const unsigned*>(pa + rA * A_LDH);
            unsigned a1 = *reinterpret_cast<const unsigned*>(pa + rB * A_LDH);
            unsigned a2 = *reinterpret_cast<const unsigned*>(pa + rA * A_LDH + 8);
            unsigned a3 = *reinterpret_cast<const unsigned*>(pa + rB * A_LDH + 8);
            unsigned a4 = *reinterpret_cast<const unsigned*>(pa + rC * A_LDH);
            unsigned a5 = *reinterpret_cast<const unsigned*>(pa + rD * A_LDH);
            unsigned a6 = *reinterpret_cast<const unsigned*>(pa + rC * A_LDH + 8);
            unsigned a7 = *reinterpret_cast<const unsigned*>(pa + rD * A_LDH + 8);
            #pragma unroll
            for (int nn = 0; nn < 8; nn++) {
                const __half* pb = sB + (nn * 8 + g) * B_LDH + k0 + 2 * tg;
                unsigned b0 = *reinterpret_cast<const unsigned*>(pb);
                unsigned b1 = *reinterpret_cast<const unsigned*>(pb + 8);
                mma16(c0[nn], a0, a1, a2, a3, b0, b1);
                mma16(c1[nn], a4, a5, a6, a7, b0, b1);
            }
        }

        // ---- bias + sigmoid -> H (fp16) into sA[:, 64:128]  (warp-private rows)
        #pragma unroll
        for (int nn = 0; nn < 8; nn++) {
            const int c = nn * 8 + 2 * tg;
            const float bb0 = sBias[c], bb1 = sBias[c + 1];
            *reinterpret_cast<__half2*>(sA + rA * A_LDH + 64 + c) =
                __floats2half2_rn(sigf(c0[nn][0] + bb0), sigf(c0[nn][1] + bb1));
            *reinterpret_cast<__half2*>(sA + rB * A_LDH + 64 + c) =
                __floats2half2_rn(sigf(c0[nn][2] + bb0), sigf(c0[nn][3] + bb1));
            *reinterpret_cast<__half2*>(sA + rC * A_LDH + 64 + c) =
                __floats2half2_rn(sigf(c1[nn][0] + bb0), sigf(c1[nn][1] + bb1));
            *reinterpret_cast<__half2*>(sA + rD * A_LDH + 64 + c) =
                __floats2half2_rn(sigf(c1[nn][2] + bb0), sigf(c1[nn][3] + bb1));
        }
    }

    // ================= Output GEMM: H[128,64] @ out_w^T + out_b =================
    for (int nc = 0; nc < 5; nc++) {   // 5 chunks of 64 cols (300 padded to 320)
        __syncthreads();
        #pragma unroll
        for (int it = 0; it < 8; it++) {
            int e  = it * THREADS + tid;
            int n  = e >> 4, k4 = e & 15;
            int gn = nc * DM + n;
            uint2 tw = make_uint2(0u, 0u);
            if (gn < NOUT) {
                float4 w = reinterpret_cast<const float4*>(outw + gn * DM)[k4];
                tw = make_uint2(pack2(w.x, w.y), pack2(w.z, w.w));
            }
            *reinterpret_cast<uint2*>(sB + n * B_LDH + k4 * 4) = tw;
        }
        if (tid < DM) {
            int gn = nc * DM + tid;
            sBias[tid] = (gn < NOUT) ? outb[gn] : 0.0f;
        }
        __syncthreads();

        float c0[8][4], c1[8][4];
        #pragma unroll
        for (int nn = 0; nn < 8; nn++) {
            c0[nn][0] = c0[nn][1] = c0[nn][2] = c0[nn][3] = 0.0f;
            c1[nn][0] = c1[nn][1] = c1[nn][2] = c1[nn][3] = 0.0f;
        }

        #pragma unroll
        for (int kk = 0; kk < 4; kk++) {     // K=64 over H
            const int ka = 64 + kk * 16;     // A = H lives in cols 64..127
            const int kb = kk * 16;
            const __half* pa = sA + ka + 2 * tg;
            unsigned a0 = *reinterpret_cast<const unsigned*>(pa + rA * A_LDH);
            unsigned a1 = *reinterpret_cast<const unsigned*>(pa + rB * A_LDH);
            unsigned a2 = *reinterpret_cast<const unsigned*>(pa + rA * A_LDH + 8);
            unsigned a3 = *reinterpret_cast<const unsigned*>(pa + rB * A_LDH + 8);
            unsigned a4 = *reinterpret_cast<const unsigned*>(pa + rC * A_LDH);
            unsigned a5 = *reinterpret_cast<const unsigned*>(pa + rD * A_LDH);
            unsigned a6 = *reinterpret_cast<const unsigned*>(pa + rC * A_LDH + 8);
            unsigned a7 = *reinterpret_cast<const unsigned*>(pa + rD * A_LDH + 8);
            #pragma unroll
            for (int nn = 0; nn < 8; nn++) {
                const __half* pb = sB + (nn * 8 + g) * B_LDH + kb + 2 * tg;
                unsigned b0 = *reinterpret_cast<const unsigned*>(pb);
                unsigned b1 = *reinterpret_cast<const unsigned*>(pb + 8);
                mma16(c0[nn], a0, a1, a2, a3, b0, b1);
                mma16(c1[nn], a4, a5, a6, a7, b0, b1);
            }
        }

        #pragma unroll
        for (int nn = 0; nn < 8; nn++) {
            const int c  = nn * 8 + 2 * tg;
            const int gc = nc * DM + c;
            if (gc < NOUT) {   // NOUT even -> pair validity uniform; addr 8B-aligned
                const float bb0 = sBias[c], bb1 = sBias[c + 1];
                float2 p;
                p.x = c0[nn][0] + bb0; p.y = c0[nn][1] + bb1;
                *reinterpret_cast<float2*>(out + (base + rA) * NOUT + gc) = p;
                p.x = c0[nn][2] + bb0; p.y = c0[nn][3] + bb1;
                *reinterpret_cast<float2*>(out + (base + rB) * NOUT + gc) = p;
                p.x = c1[nn][0] + bb0; p.y = c1[nn][1] + bb1;
                *reinterpret_cast<float2*>(out + (base + rC) * NOUT + gc) = p;
                p.x = c1[nn][2] + bb0; p.y = c1[nn][3] + bb1;
                *reinterpret_cast<float2*>(out + (base + rD) * NOUT + gc) = p;
            }
        }
    }
}

extern "C" void kernel_launch(void* const* d_in, const int* in_sizes, int n_in,
                              void* d_out, int out_size) {
    const int*   acts = (const int*)  d_in[0];
    const float* emb  = (const float*)d_in[1];
    const float* Mw   = (const float*)d_in[2];
    const float* Mb   = (const float*)d_in[3];
    const float* Ww   = (const float*)d_in[4];
    const float* Wb   = (const float*)d_in[5];
    const float* outw = (const float*)d_in[6];
    const float* outb = (const float*)d_in[7];
    float* out = (float*)d_out;

    const int smem = (ROWS * A_LDH + DM * B_LDH) * (int)sizeof(__half)
                   + DM * (int)sizeof(float);   // ~52.5 KB -> 4 CTAs/SM
    cudaFuncSetAttribute(carnn_kernel, cudaFuncAttributeMaxDynamicSharedMemorySize, smem);

    const int B = in_sizes[0] / SEQ;   // 65536
    carnn_kernel<<<B / ROWS, THREADS, smem>>>(acts, emb, Mw, Mb, Ww, Wb, outw, outb, out);
}

// round 11
// speedup vs baseline: 1.7490x; 1.0578x over previous
#include <cuda_runtime.h>
#include <cuda_fp16.h>
#include <cstdint>

#define THREADS 128
#define ROWS    128     // batch rows per block
#define DM      64
#define SEQ     9
#define NOUT    300
#define A_LDH   136     // leading dim in halves -> conflict-free LDSM phases (68w stride)
#define B_LDH   136

__device__ __forceinline__ unsigned pack2(float a, float b) {
    __half2 h = __floats2half2_rn(a, b);
    return *reinterpret_cast<unsigned*>(&h);
}

__device__ __forceinline__ float sigf(float v) {
    return __fdividef(1.0f, 1.0f + __expf(-v));
}

__device__ __forceinline__ uint32_t smem_u32(const void* p) {
    uint32_t a;
    asm("{ .reg .u64 t; cvta.to.shared.u64 t, %1; cvt.u32.u64 %0, t; }" : "=r"(a) : "l"(p));
    return a;
}

__device__ __forceinline__ void ldsm4(unsigned& r0, unsigned& r1, unsigned& r2, unsigned& r3,
                                      uint32_t addr) {
    asm volatile("ldmatrix.sync.aligned.m8n8.x4.shared.b16 {%0,%1,%2,%3}, [%4];"
                 : "=r"(r0), "=r"(r1), "=r"(r2), "=r"(r3) : "r"(addr));
}

__device__ __forceinline__ void mma16(float* c,
                                      unsigned a0, unsigned a1, unsigned a2, unsigned a3,
                                      unsigned b0, unsigned b1) {
    asm volatile(
        "mma.sync.aligned.m16n8k16.row.col.f32.f16.f16.f32 "
        "{%0,%1,%2,%3}, {%4,%5,%6,%7}, {%8,%9}, {%0,%1,%2,%3};"
        : "+f"(c[0]), "+f"(c[1]), "+f"(c[2]), "+f"(c[3])
        : "r"(a0), "r"(a1), "r"(a2), "r"(a3), "r"(b0), "r"(b1));
}

__global__ void __launch_bounds__(THREADS, 4) carnn_kernel(
    const int*   __restrict__ acts,   // [B, 9] int32
    const float* __restrict__ emb,    // [301, 64]
    const float* __restrict__ Mw,     // [50, 64, 64]
    const float* __restrict__ Mb,     // [50, 64]
    const float* __restrict__ Ww,     // [56, 64, 64]
    const float* __restrict__ Wb,     // [56, 64]
    const float* __restrict__ outw,   // [300, 64]
    const float* __restrict__ outb,   // [300]
    float*       __restrict__ out)    // [B, 300]
{
    extern __shared__ __align__(16) char smem_raw[];
    __half* sA    = reinterpret_cast<__half*>(smem_raw);          // [128][A_LDH]: 0..63 X, 64..127 H
    __half* sB    = sA + ROWS * A_LDH;                            // [64][B_LDH]: n-major weights
    float*  sBias = reinterpret_cast<float*>(sB + DM * B_LDH);    // [64]

    const int tid  = threadIdx.x;
    const int lane = tid & 31;
    const int warp = tid >> 5;
    const int g    = lane >> 2;          // groupID
    const int tg   = lane & 3;           // threadID_in_group
    const int rA = warp * 32 + g;        // warp tile: M=32 x N=64
    const int rB = rA + 8;
    const int rC = rA + 16;
    const int rD = rA + 24;
    const long base = (long)blockIdx.x * ROWS;

    // ldmatrix per-lane base addresses (bytes, shared space)
    // A x4: lanes 0-15 -> rows w32+(lane&15) @k, lanes 16-31 -> same rows @k+8
    const uint32_t sA_u = smem_u32(sA);
    const uint32_t sB_u = smem_u32(sB);
    const int aRow = warp * 32 + (lane & 15);
    const int aK   = ((lane >> 4) & 1) * 8;
    const uint32_t aBase0 = sA_u + 2u * (uint32_t)(aRow * A_LDH + aK);
    const uint32_t aBase1 = aBase0 + 2u * 16u * A_LDH;
    // B x4: lanes 0-7 n-rows, lanes 8-15 same @k+8, lanes 16-31 next 8 n-rows
    const int bRow = (lane & 7) + ((lane & 16) ? 8 : 0);
    const int bK   = (lane & 8) ? 8 : 0;
    const uint32_t bBase = sB_u + 2u * (uint32_t)(bRow * B_LDH + bK);
    const uint32_t bNP   = 2u * 16u * B_LDH;   // bytes per 16 n-rows

    // hoist this row's action ids (thread t <-> batch row t)
    int myAct[SEQ];
    {
        const int* ap = acts + (base + tid) * SEQ;
        #pragma unroll
        for (int s = 0; s < SEQ; s++) myAct[s] = ap[s];
    }

    // ================= RNN: 9 steps =================
    for (int s = 0; s < SEQ; s++) {
        __syncthreads();  // prior step's sA/sB reads done before overwrite

        // ---- gather X_s -> sA[tid][0:64] (fp16), one thread per row
        {
            const float4* er  = reinterpret_cast<const float4*>(emb + myAct[s] * DM);
            uint4*        dst = reinterpret_cast<uint4*>(sA + tid * A_LDH);
            #pragma unroll
            for (int j = 0; j < 16; j += 2) {
                float4 v0 = er[j], v1 = er[j + 1];
                uint4 w;
                w.x = pack2(v0.x, v0.y); w.y = pack2(v0.z, v0.w);
                w.z = pack2(v1.x, v1.y); w.w = pack2(v1.z, v1.w);
                dst[j >> 1] = w;
            }
        }
        // ---- weights: sB[n][0..63] = Mw_s[n][:], sB[n][64..127] = Ww_s[n][:]
        {
            const float4* Mws = reinterpret_cast<const float4*>(Mw + s * DM * DM);
            const float4* Wws = reinterpret_cast<const float4*>(Ww + s * DM * DM);
            #pragma unroll
            for (int it = 0; it < 8; it++) {          // 1024 float4s / 128 threads
                int e  = it * THREADS + tid;
                int n  = e >> 4, k4 = e & 15;
                float4 m = Mws[e], w = Wws[e];
                uint2 tm = make_uint2(pack2(m.x, m.y), pack2(m.z, m.w));
                uint2 tw = make_uint2(pack2(w.x, w.y), pack2(w.z, w.w));
                *reinterpret_cast<uint2*>(sB + n * B_LDH + k4 * 4)      = tm;
                *reinterpret_cast<uint2*>(sB + n * B_LDH + 64 + k4 * 4) = tw;
            }
            if (tid < DM) sBias[tid] = Mb[s * DM + tid] + Wb[s * DM + tid];
        }
        __syncthreads();

        // ---- [X|H] @ [Mw;Ww]^T : per warp M=32, N=64, K=128 (K=64 at s=0, h0=0)
        float c0[8][4], c1[8][4];
        #pragma unroll
        for (int nn = 0; nn < 8; nn++) {
            c0[nn][0] = c0[nn][1] = c0[nn][2] = c0[nn][3] = 0.0f;
            c1[nn][0] = c1[nn][1] = c1[nn][2] = c1[nn][3] = 0.0f;
        }

        const int Kc = (s == 0) ? 4 : 8;     // chunks of K=16
        #pragma unroll
        for (int kk = 0; kk < 8; kk++) {
            if (kk >= Kc) break;
            const uint32_t k0b = (uint32_t)kk * 32u;   // 16 halves
            unsigned a0, a1, a2, a3, a4, a5, a6, a7;
            ldsm4(a0, a1, a2, a3, aBase0 + k0b);
            ldsm4(a4, a5, a6, a7, aBase1 + k0b);
            #pragma unroll
            for (int np = 0; np < 4; np++) {
                unsigned b0, b1, b2, b3;
                ldsm4(b0, b1, b2, b3, bBase + np * bNP + k0b);
                mma16(c0[2 * np],     a0, a1, a2, a3, b0, b1);
                mma16(c1[2 * np],     a4, a5, a6, a7, b0, b1);
                mma16(c0[2 * np + 1], a0, a1, a2, a3, b2, b3);
                mma16(c1[2 * np + 1], a4, a5, a6, a7, b2, b3);
            }
        }

        // ---- bias + sigmoid -> H (fp16) into sA[:, 64:128]  (warp-private rows)
        #pragma unroll
        for (int nn = 0; nn < 8; nn++) {
            const int c = nn * 8 + 2 * tg;
            const float bb0 = sBias[c], bb1 = sBias[c + 1];
            *reinterpret_cast<__half2*>(sA + rA * A_LDH + 64 + c) =
                __floats2half2_rn(sigf(c0[nn][0] + bb0), sigf(c0[nn][1] + bb1));
            *reinterpret_cast<__half2*>(sA + rB * A_LDH + 64 + c) =
                __floats2half2_rn(sigf(c0[nn][2] + bb0), sigf(c0[nn][3] + bb1));
            *reinterpret_cast<__half2*>(sA + rC * A_LDH + 64 + c) =
                __floats2half2_rn(sigf(c1[nn][0] + bb0), sigf(c1[nn][1] + bb1));
            *reinterpret_cast<__half2*>(sA + rD * A_LDH + 64 + c) =
                __floats2half2_rn(sigf(c1[nn][2] + bb0), sigf(c1[nn][3] + bb1));
        }
    }

    // ================= Output GEMM: H[128,64] @ out_w^T + out_b =================
    const uint32_t aHOfs = 2u * 64u;   // H lives in cols 64..127
    for (int nc = 0; nc < 5; nc++) {   // 5 chunks of 64 cols (300 padded to 320)
        __syncthreads();
        #pragma unroll
        for (int it = 0; it < 8; it++) {
            int e  = it * THREADS + tid;
            int n  = e >> 4, k4 = e & 15;
            int gn = nc * DM + n;
            uint2 tw = make_uint2(0u, 0u);
            if (gn < NOUT) {
                float4 w = reinterpret_cast<const float4*>(outw + gn * DM)[k4];
                tw = make_uint2(pack2(w.x, w.y), pack2(w.z, w.w));
            }
            *reinterpret_cast<uint2*>(sB + n * B_LDH + k4 * 4) = tw;
        }
        if (tid < DM) {
            int gn = nc * DM + tid;
            sBias[tid] = (gn < NOUT) ? outb[gn] : 0.0f;
        }
        __syncthreads();

        float c0[8][4], c1[8][4];
        #pragma unroll
        for (int nn = 0; nn < 8; nn++) {
            c0[nn][0] = c0[nn][1] = c0[nn][2] = c0[nn][3] = 0.0f;
            c1[nn][0] = c1[nn][1] = c1[nn][2] = c1[nn][3] = 0.0f;
        }

        #pragma unroll
        for (int kk = 0; kk < 4; kk++) {     // K=64 over H
            const uint32_t kab = aHOfs + (uint32_t)kk * 32u;
            const uint32_t kbb = (uint32_t)kk * 32u;
            unsigned a0, a1, a2, a3, a4, a5, a6, a7;
            ldsm4(a0, a1, a2, a3, aBase0 + kab);
            ldsm4(a4, a5, a6, a7, aBase1 + kab);
            #pragma unroll
            for (int np = 0; np < 4; np++) {
                unsigned b0, b1, b2, b3;
                ldsm4(b0, b1, b2, b3, bBase + np * bNP + kbb);
                mma16(c0[2 * np],     a0, a1, a2, a3, b0, b1);
                mma16(c1[2 * np],     a4, a5, a6, a7, b0, b1);
                mma16(c0[2 * np + 1], a0, a1, a2, a3, b2, b3);
                mma16(c1[2 * np + 1], a4, a5, a6, a7, b2, b3);
            }
        }

        #pragma unroll
        for (int nn = 0; nn < 8; nn++) {
            const int c  = nn * 8 + 2 * tg;
            const int gc = nc * DM + c;
            if (gc < NOUT) {   // NOUT even -> pair validity uniform; addr 8B-aligned
                const float bb0 = sBias[c], bb1 = sBias[c + 1];
                float2 p;
                p.x = c0[nn][0] + bb0; p.y = c0[nn][1] + bb1;
                *reinterpret_cast<float2*>(out + (base + rA) * NOUT + gc) = p;
                p.x = c0[nn][2] + bb0; p.y = c0[nn][3] + bb1;
                *reinterpret_cast<float2*>(out + (base + rB) * NOUT + gc) = p;
                p.x = c1[nn][0] + bb0; p.y = c1[nn][1] + bb1;
                *reinterpret_cast<float2*>(out + (base + rC) * NOUT + gc) = p;
                p.x = c1[nn][2] + bb0; p.y = c1[nn][3] + bb1;
                *reinterpret_cast<float2*>(out + (base + rD) * NOUT + gc) = p;
            }
        }
    }
}

extern "C" void kernel_launch(void* const* d_in, const int* in_sizes, int n_in,
                              void* d_out, int out_size) {
    const int*   acts = (const int*)  d_in[0];
    const float* emb  = (const float*)d_in[1];
    const float* Mw   = (const float*)d_in[2];
    const float* Mb   = (const float*)d_in[3];
    const float* Ww   = (const float*)d_in[4];
    const float* Wb   = (const float*)d_in[5];
    const float* outw = (const float*)d_in[6];
    const float* outb = (const float*)d_in[7];
    float* out = (float*)d_out;

    const int smem = (ROWS * A_LDH + DM * B_LDH) * (int)sizeof(__half)
                   + DM * (int)sizeof(float);   // ~52.5 KB -> 4 CTAs/SM
    cudaFuncSetAttribute(carnn_kernel, cudaFuncAttributeMaxDynamicSharedMemorySize, smem);

    const int B = in_sizes[0] / SEQ;   // 65536
    carnn_kernel<<<B / ROWS, THREADS, smem>>>(acts, emb, Mw, Mb, Ww, Wb, outw, outb, out);
}

// round 12
// speedup vs baseline: 2.1919x; 1.2532x over previous
#include <cuda_runtime.h>
#include <cuda_fp16.h>
#include <cstdint>

#define THREADS 256
#define ROWS    256     // batch rows per block
#define DM      64
#define SEQ     9
#define NOUT    300
#define NPAD    320
#define A_LDH   136     // halves; 272B row stride -> conflict-free LDSM/STS phases
#define B_LDH   136
#define BUFB    (DM * B_LDH * 2)   // bytes per B buffer (17408)

// ---------------- packed fp16 parameter store (written by prep kernel) ----------------
__device__ __half d_wPack[SEQ * DM * 128];   // [s][n][k]: k<64 Mw, k>=64 Ww
__device__ __half d_embPack[301 * DM];       // fp16 embedding table
__device__ __half d_owPack[NPAD * DM];       // out_w padded with zeros to 320 rows
__device__ float  d_biasAll[SEQ * DM];       // Mb + Wb
__device__ float  d_obPack[NPAD];            // out_b padded

__global__ void prep_kernel(const float* __restrict__ emb,
                            const float* __restrict__ Mw, const float* __restrict__ Mb,
                            const float* __restrict__ Ww, const float* __restrict__ Wb,
                            const float* __restrict__ outw, const float* __restrict__ outb) {
    const int NW = SEQ * DM * 128, NE = 301 * DM, NO = NPAD * DM, NB = SEQ * DM;
    int i = blockIdx.x * blockDim.x + threadIdx.x;
    if (i < NW) {
        int s = i >> 13, r = i & 8191, n = r >> 7, k = r & 127;
        float v = (k < DM) ? Mw[s * 4096 + n * DM + k] : Ww[s * 4096 + n * DM + (k - DM)];
        d_wPack[i] = __float2half(v);
        return;
    }
    int j = i - NW;
    if (j < NE) { d_embPack[j] = __float2half(emb[j]); return; }
    int k2 = j - NE;
    if (k2 < NO) {
        int gn = k2 >> 6;
        d_owPack[k2] = (gn < NOUT) ? __float2half(outw[k2]) : __half(0.0f);
        return;
    }
    int m = k2 - NO;
    if (m < NB) { d_biasAll[m] = Mb[m] + Wb[m]; return; }
    int p = m - NB;
    if (p < NPAD) d_obPack[p] = (p < NOUT) ? outb[p] : 0.0f;
}

// ---------------- device helpers ----------------
__device__ __forceinline__ float sigf(float v) {
    return __fdividef(1.0f, 1.0f + __expf(-v));
}
__device__ __forceinline__ uint32_t smem_u32(const void* p) {
    uint32_t a;
    asm("{ .reg .u64 t; cvta.to.shared.u64 t, %1; cvt.u32.u64 %0, t; }" : "=r"(a) : "l"(p));
    return a;
}
__device__ __forceinline__ void cpasync16(uint32_t dst, const void* src) {
    asm volatile("cp.async.cg.shared.global [%0], [%1], 16;" :: "r"(dst), "l"(src));
}
#define CP_COMMIT() asm volatile("cp.async.commit_group;" ::: "memory")
#define CP_WAIT0()  asm volatile("cp.async.wait_group 0;" ::: "memory")

__device__ __forceinline__ void ldsm4(unsigned& r0, unsigned& r1, unsigned& r2, unsigned& r3,
                                      uint32_t addr) {
    asm volatile("ldmatrix.sync.aligned.m8n8.x4.shared.b16 {%0,%1,%2,%3}, [%4];"
                 : "=r"(r0), "=r"(r1), "=r"(r2), "=r"(r3) : "r"(addr));
}
__device__ __forceinline__ void mma16(float* c,
                                      unsigned a0, unsigned a1, unsigned a2, unsigned a3,
                                      unsigned b0, unsigned b1) {
    asm volatile(
        "mma.sync.aligned.m16n8k16.row.col.f32.f16.f16.f32 "
        "{%0,%1,%2,%3}, {%4,%5,%6,%7}, {%8,%9}, {%0,%1,%2,%3};"
        : "+f"(c[0]), "+f"(c[1]), "+f"(c[2]), "+f"(c[3])
        : "r"(a0), "r"(a1), "r"(a2), "r"(a3), "r"(b0), "r"(b1));
}

// ---------------- main kernel ----------------
__global__ void __launch_bounds__(THREADS, 2) carnn_kernel(
    const int* __restrict__ acts,    // [B, 9]
    float*     __restrict__ out)     // [B, 300]
{
    extern __shared__ __align__(16) char smem_raw[];
    __half* sA    = reinterpret_cast<__half*>(smem_raw);       // [256][A_LDH]: 0..63 X, 64..127 H
    __half* sB    = sA + ROWS * A_LDH;                         // 2 x [64][B_LDH]
    float*  sBiasAll = reinterpret_cast<float*>(sB + 2 * DM * B_LDH);  // [9*64]
    float*  sBiasEp  = sBiasAll + SEQ * DM;                    // [320]

    const int tid  = threadIdx.x;
    const int lane = tid & 31;
    const int warp = tid >> 5;
    const int g    = lane >> 2;
    const int tg   = lane & 3;
    const int rA = warp * 32 + g;     // warp tile M=32 x N=64
    const int rB = rA + 8;
    const int rC = rA + 16;
    const int rD = rA + 24;
    const long base = (long)blockIdx.x * ROWS;

    const uint32_t sA_u = smem_u32(sA);
    const uint32_t sB_u = smem_u32(sB);
    // ldmatrix lane bases
    const int aRow = warp * 32 + (lane & 15);
    const int aK   = ((lane >> 4) & 1) * 8;
    const uint32_t aBase0 = sA_u + 2u * (uint32_t)(aRow * A_LDH + aK);
    const uint32_t aBase1 = aBase0 + 2u * 16u * A_LDH;
    const int bRow = (lane & 7) + ((lane & 16) ? 8 : 0);
    const int bK   = (lane & 8) ? 8 : 0;
    const uint32_t bBase = sB_u + 2u * (uint32_t)(bRow * B_LDH + bK);
    const uint32_t bNP   = 2u * 16u * B_LDH;

    // hoist action ids (thread t <-> row t)
    int myAct[SEQ];
    {
        const int* ap = acts + (base + tid) * SEQ;
        #pragma unroll
        for (int s = 0; s < SEQ; s++) myAct[s] = ap[s];
    }

    // issue cp.async for step-s weights into buffer b (64 rows x 128 halves = 1024 x16B)
    auto issue_w = [&](int s, int b) {
        const char* src = reinterpret_cast<const char*>(d_wPack + s * (DM * 128));
        const uint32_t dst0 = sB_u + (uint32_t)b * BUFB;
        #pragma unroll
        for (int it = 0; it < 4; it++) {
            int e = it * THREADS + tid;
            int n = e >> 4, k16 = e & 15;
            cpasync16(dst0 + n * (B_LDH * 2) + k16 * 16, src + e * 16);
        }
    };
    // epilogue chunk nc (64 rows x 64 halves = 512 x16B)
    auto issue_o = [&](int nc, int b) {
        const char* src = reinterpret_cast<const char*>(d_owPack + nc * (DM * DM));
        const uint32_t dst0 = sB_u + (uint32_t)b * BUFB;
        #pragma unroll
        for (int it = 0; it < 2; it++) {
            int e = it * THREADS + tid;
            int n = e >> 3, k16 = e & 7;
            cpasync16(dst0 + n * (B_LDH * 2) + k16 * 16, src + e * 16);
        }
    };

    // prologue: weights for step 0 + bias preload
    issue_w(0, 0);
    CP_COMMIT();
    for (int i = tid; i < SEQ * DM; i += THREADS) sBiasAll[i] = d_biasAll[i];
    for (int i = tid; i < NPAD; i += THREADS)     sBiasEp[i]  = d_obPack[i];

    // ================= RNN: 9 steps =================
    for (int s = 0; s < SEQ; s++) {
        CP_WAIT0();
        __syncthreads();           // weights[s] visible; prev readers of other buf done
        if (s + 1 < SEQ) issue_w(s + 1, (s + 1) & 1);
        else             issue_o(0, 1);
        CP_COMMIT();
        const uint32_t bufB = (uint32_t)(s & 1) * BUFB;

        // X_s row load (fp16, 128B) — in flight during H-chunk compute
        uint4 xr[8];
        {
            const uint4* ep = reinterpret_cast<const uint4*>(d_embPack + myAct[s] * DM);
            #pragma unroll
            for (int j = 0; j < 8; j++) xr[j] = ep[j];
        }

        float c0[8][4], c1[8][4];
        #pragma unroll
        for (int nn = 0; nn < 8; nn++) {
            c0[nn][0] = c0[nn][1] = c0[nn][2] = c0[nn][3] = 0.0f;
            c1[nn][0] = c1[nn][1] = c1[nn][2] = c1[nn][3] = 0.0f;
        }

        // H part first (kk = 4..7) — H rows are warp-private, written last step
        if (s > 0) {
            #pragma unroll
            for (int kk = 4; kk < 8; kk++) {
                const uint32_t k0b = (uint32_t)kk * 32u;
                unsigned a0, a1, a2, a3, a4, a5, a6, a7;
                ldsm4(a0, a1, a2, a3, aBase0 + k0b);
                ldsm4(a4, a5, a6, a7, aBase1 + k0b);
                #pragma unroll
                for (int np = 0; np < 4; np++) {
                    unsigned b0, b1, b2, b3;
                    ldsm4(b0, b1, b2, b3, bBase + bufB + np * bNP + k0b);
                    mma16(c0[2 * np],     a0, a1, a2, a3, b0, b1);
                    mma16(c1[2 * np],     a4, a5, a6, a7, b0, b1);
                    mma16(c0[2 * np + 1], a0, a1, a2, a3, b2, b3);
                    mma16(c1[2 * np + 1], a4, a5, a6, a7, b2, b3);
                }
            }
        }

        // stage X_s (warp-private rows: thread t -> row t of its own warp)
        {
            uint4* xd = reinterpret_cast<uint4*>(sA + tid * A_LDH);
            #pragma unroll
            for (int j = 0; j < 8; j++) xd[j] = xr[j];
        }
        __syncwarp();

        // X part (kk = 0..3)
        #pragma unroll
        for (int kk = 0; kk < 4; kk++) {
            const uint32_t k0b = (uint32_t)kk * 32u;
            unsigned a0, a1, a2, a3, a4, a5, a6, a7;
            ldsm4(a0, a1, a2, a3, aBase0 + k0b);
            ldsm4(a4, a5, a6, a7, aBase1 + k0b);
            #pragma unroll
            for (int np = 0; np < 4; np++) {
                unsigned b0, b1, b2, b3;
                ldsm4(b0, b1, b2, b3, bBase + bufB + np * bNP + k0b);
                mma16(c0[2 * np],     a0, a1, a2, a3, b0, b1);
                mma16(c1[2 * np],     a4, a5, a6, a7, b0, b1);
                mma16(c0[2 * np + 1], a0, a1, a2, a3, b2, b3);
                mma16(c1[2 * np + 1], a4, a5, a6, a7, b2, b3);
            }
        }

        // bias + sigmoid -> H (fp16), warp-private rows
        const float* bs = sBiasAll + s * DM;
        #pragma unroll
        for (int nn = 0; nn < 8; nn++) {
            const int c = nn * 8 + 2 * tg;
            const float bb0 = bs[c], bb1 = bs[c + 1];
            *reinterpret_cast<__half2*>(sA + rA * A_LDH + DM + c) =
                __floats2half2_rn(sigf(c0[nn][0] + bb0), sigf(c0[nn][1] + bb1));
            *reinterpret_cast<__half2*>(sA + rB * A_LDH + DM + c) =
                __floats2half2_rn(sigf(c0[nn][2] + bb0), sigf(c0[nn][3] + bb1));
            *reinterpret_cast<__half2*>(sA + rC * A_LDH + DM + c) =
                __floats2half2_rn(sigf(c1[nn][0] + bb0), sigf(c1[nn][1] + bb1));
            *reinterpret_cast<__half2*>(sA + rD * A_LDH + DM + c) =
                __floats2half2_rn(sigf(c1[nn][2] + bb0), sigf(c1[nn][3] + bb1));
        }
        __syncwarp();
    }

    // ================= Output GEMM: H[256,64] @ out_w^T + out_b =================
    // hoist H A-fragments (warp-private, stable across chunks)
    unsigned aH[4][8];
    #pragma unroll
    for (int kk = 0; kk < 4; kk++) {
        const uint32_t kab = 128u + (uint32_t)kk * 32u;    // H at byte col 128
        ldsm4(aH[kk][0], aH[kk][1], aH[kk][2], aH[kk][3], aBase0 + kab);
        ldsm4(aH[kk][4], aH[kk][5], aH[kk][6], aH[kk][7], aBase1 + kab);
    }

    for (int nc = 0; nc < 5; nc++) {
        CP_WAIT0();
        __syncthreads();
        if (nc + 1 < 5) { issue_o(nc + 1, nc & 1); CP_COMMIT(); }
        const uint32_t bufB = (uint32_t)((nc + 1) & 1) * BUFB;

        float c0[8][4], c1[8][4];
        #pragma unroll
        for (int nn = 0; nn < 8; nn++) {
            c0[nn][0] = c0[nn][1] = c0[nn][2] = c0[nn][3] = 0.0f;
            c1[nn][0] = c1[nn][1] = c1[nn][2] = c1[nn][3] = 0.0f;
        }

        #pragma unroll
        for (int kk = 0; kk < 4; kk++) {
            const uint32_t kbb = (uint32_t)kk * 32u;
            #pragma unroll
            for (int np = 0; np < 4; np++) {
                unsigned b0, b1, b2, b3;
                ldsm4(b0, b1, b2, b3, bBase + bufB + np * bNP + kbb);
                mma16(c0[2 * np],     aH[kk][0], aH[kk][1], aH[kk][2], aH[kk][3], b0, b1);
                mma16(c1[2 * np],     aH[kk][4], aH[kk][5], aH[kk][6], aH[kk][7], b0, b1);
                mma16(c0[2 * np + 1], aH[kk][0], aH[kk][1], aH[kk][2], aH[kk][3], b2, b3);
                mma16(c1[2 * np + 1], aH[kk][4], aH[kk][5], aH[kk][6], aH[kk][7], b2, b3);
            }
        }

        const float* be = sBiasEp + nc * DM;
        #pragma unroll
        for (int nn = 0; nn < 8; nn++) {
            const int c  = nn * 8 + 2 * tg;
            const int gc = nc * DM + c;
            if (gc < NOUT) {   // pair-uniform, 8B aligned
                const float bb0 = be[c], bb1 = be[c + 1];
                float2 p;
                p.x = c0[nn][0] + bb0; p.y = c0[nn][1] + bb1;
                *reinterpret_cast<float2*>(out + (base + rA) * NOUT + gc) = p;
                p.x = c0[nn][2] + bb0; p.y = c0[nn][3] + bb1;
                *reinterpret_cast<float2*>(out + (base + rB) * NOUT + gc) = p;
                p.x = c1[nn][0] + bb0; p.y = c1[nn][1] + bb1;
                *reinterpret_cast<float2*>(out + (base + rC) * NOUT + gc) = p;
                p.x = c1[nn][2] + bb0; p.y = c1[nn][3] + bb1;
                *reinterpret_cast<float2*>(out + (base + rD) * NOUT + gc) = p;
            }
        }
    }
}

extern "C" void kernel_launch(void* const* d_in, const int* in_sizes, int n_in,
                              void* d_out, int out_size) {
    const int*   acts = (const int*)  d_in[0];
    const float* emb  = (const float*)d_in[1];
    const float* Mw   = (const float*)d_in[2];
    const float* Mb   = (const float*)d_in[3];
    const float* Ww   = (const float*)d_in[4];
    const float* Wb   = (const float*)d_in[5];
    const float* outw = (const float*)d_in[6];
    const float* outb = (const float*)d_in[7];
    float* out = (float*)d_out;

    const int NPREP = SEQ * DM * 128 + 301 * DM + NPAD * DM + SEQ * DM + NPAD;
    prep_kernel<<<(NPREP + 255) / 256, 256>>>(emb, Mw, Mb, Ww, Wb, outw, outb);

    const int smem = (ROWS * A_LDH + 2 * DM * B_LDH) * (int)sizeof(__half)
                   + (SEQ * DM + NPAD) * (int)sizeof(float);   // ~105.5 KB -> 2 CTAs/SM
    cudaFuncSetAttribute(carnn_kernel, cudaFuncAttributeMaxDynamicSharedMemorySize, smem);

    const int B = in_sizes[0] / SEQ;   // 65536
    carnn_kernel<<<B / ROWS, THREADS, smem>>>(acts, out);
}

// round 16
// speedup vs baseline: 2.3018x; 1.0502x over previous
#include <cuda_runtime.h>
#include <cuda_fp16.h>
#include <cstdint>

#define THREADS 512
#define ROWS    512
#define DM      64
#define SEQ     9
#define NOUT    300

// ---------------- packed parameter store ----------------
__device__ __half d_E[SEQ * 301 * DM];   // E[s][a][c] = emb[a].Mw[s][c] + Mb + Wb
__device__ __half d_wwPack[8 * 4096];    // Ww s=1..8, SW128-swizzled [64n x 64k]
__device__ __half d_owPack[5 * 4096];    // out_w 5 chunks, swizzled, zero-padded
__device__ float  d_obPack[320];         // out_b padded

__global__ void prep_E(const float* __restrict__ emb, const float* __restrict__ Mw,
                       const float* __restrict__ Mb, const float* __restrict__ Wb) {
    int b = blockIdx.x;                 // s*301 + a
    int s = b / 301, a = b % 301;
    int c = threadIdx.x;                // 0..63
    const float4* er = reinterpret_cast<const float4*>(emb + a * DM);
    const float4* mr = reinterpret_cast<const float4*>(Mw + (s * DM + c) * DM);
    float acc = Mb[s * DM + c] + Wb[s * DM + c];
    #pragma unroll
    for (int i = 0; i < 16; i++) {
        float4 e = er[i], m = mr[i];
        acc += e.x * m.x + e.y * m.y + e.z * m.z + e.w * m.w;
    }
    d_E[b * DM + c] = __float2half(acc);
}

__global__ void prep_pack(const float* __restrict__ Ww, const float* __restrict__ outw,
                          const float* __restrict__ outb) {
    const int N1 = 8 * 4096, N2 = 5 * 4096;
    int i = blockIdx.x * blockDim.x + threadIdx.x;
    if (i < N1) {
        int t = i >> 12, r = i & 4095, n = r >> 6, k = r & 63;
        float v = Ww[(t + 1) * 4096 + n * DM + k];
        uint32_t sw = (uint32_t)n * 128u + (((uint32_t)k * 2u) ^ (((uint32_t)(n & 7)) << 4));
        d_wwPack[t * 4096 + (sw >> 1)] = __float2half(v);
        return;
    }
    int j = i - N1;
    if (j < N2) {
        int nc = j >> 12, r = j & 4095, n = r >> 6, k = r & 63;
        int gn = nc * DM + n;
        float v = (gn < NOUT) ? outw[gn * DM + k] : 0.0f;
        uint32_t sw = (uint32_t)n * 128u + (((uint32_t)k * 2u) ^ (((uint32_t)(n & 7)) << 4));
        d_owPack[nc * 4096 + (sw >> 1)] = __float2half(v);
        return;
    }
    int p = j - N2;
    if (p < 320) d_obPack[p] = (p < NOUT) ? outb[p] : 0.0f;
}

// ---------------- device helpers ----------------
__device__ __forceinline__ uint32_t smem_u32(const void* p) {
    uint32_t a;
    asm("{ .reg .u64 t; cvta.to.shared.u64 t, %1; cvt.u32.u64 %0, t; }" : "=r"(a) : "l"(p));
    return a;
}
__device__ __forceinline__ unsigned pack2(float a, float b) {
    __half2 h = __floats2half2_rn(a, b);
    return *reinterpret_cast<unsigned*>(&h);
}
__device__ __forceinline__ float sigf(float v) {
    float t;
    asm("tanh.approx.f32 %0, %1;" : "=f"(t) : "f"(v * 0.5f));
    return fmaf(0.5f, t, 0.5f);
}
__device__ __forceinline__ unsigned sigpack0(unsigned eh) {
    float2 e = __half22float2(*reinterpret_cast<__half2*>(&eh));
    return pack2(sigf(e.x), sigf(e.y));
}
__device__ __forceinline__ unsigned sigpack2(unsigned eh, float a0, float a1) {
    float2 e = __half22float2(*reinterpret_cast<__half2*>(&eh));
    return pack2(sigf(e.x + a0), sigf(e.y + a1));
}
__device__ __forceinline__ void cpasync16(uint32_t dst, const void* src) {
    asm volatile("cp.async.cg.shared.global [%0], [%1], 16;" :: "r"(dst), "l"(src));
}
__device__ __forceinline__ void cpasync4(uint32_t dst, const void* src) {
    asm volatile("cp.async.ca.shared.global [%0], [%1], 4;" :: "r"(dst), "l"(src));
}
#define CP_COMMIT() asm volatile("cp.async.commit_group;" ::: "memory")
#define CP_WAITG(n) asm volatile("cp.async.wait_group %0;" :: "n"(n) : "memory")

__device__ __forceinline__ void ldsm4(unsigned& r0, unsigned& r1, unsigned& r2, unsigned& r3,
                                      uint32_t addr) {
    asm volatile("ldmatrix.sync.aligned.m8n8.x4.shared.b16 {%0,%1,%2,%3}, [%4];"
                 : "=r"(r0), "=r"(r1), "=r"(r2), "=r"(r3) : "r"(addr));
}
__device__ __forceinline__ void mma16(float* c,
                                      unsigned a0, unsigned a1, unsigned a2, unsigned a3,
                                      unsigned b0, unsigned b1) {
    asm volatile(
        "mma.sync.aligned.m16n8k16.row.col.f32.f16.f16.f32 "
        "{%0,%1,%2,%3}, {%4,%5,%6,%7}, {%8,%9}, {%0,%1,%2,%3};"
        : "+f"(c[0]), "+f"(c[1]), "+f"(c[2]), "+f"(c[3])
        : "r"(a0), "r"(a1), "r"(a2), "r"(a3), "r"(b0), "r"(b1));
}

// ---------------- main kernel ----------------
// SMEM: [0]      sW: 8 x 8192   (Ww tiles, steps 1..8)
//       [65536]  sE0: 512 x 128 (E buffer, parity 0; epilogue: ow slots)
//       [131072] sE1: 512 x 128 (E buffer, parity 1)
//       [196608] biasEp: 320 f32        total 197888 B -> 1 CTA/SM
__global__ void __launch_bounds__(THREADS) carnn_kernel(
    const int* __restrict__ acts, float* __restrict__ out)
{
    extern __shared__ __align__(128) char smem[];
    const uint32_t sbase = smem_u32(smem);
    const uint32_t sW = sbase;
    const uint32_t sEb[2] = { sbase + 65536u, sbase + 131072u };
    float* biasEp = reinterpret_cast<float*>(smem + 196608);

    const int tid = threadIdx.x, lane = tid & 31, warp = tid >> 5;
    const int g = lane >> 2, tg = lane & 3;
    const int rA = warp * 32 + g, rB = rA + 8, rC = rA + 16, rD = rA + 24;
    const long base = (long)blockIdx.x * ROWS;

    // B ldsm lane addressing (swizzled 128B rows)
    const int nb = (lane & 7) + ((lane & 16) >> 1);
    const uint32_t bOff = (uint32_t)nb * 128u
                        + ((uint32_t)((lane & 8) << 1) ^ ((uint32_t)((nb & 7) << 4) & 16u));
    const uint32_t bXsw = (uint32_t)((nb & 7) << 4) & 0x60u;
    uint32_t kkB[4];
    #pragma unroll
    for (int kk = 0; kk < 4; kk++) kkB[kk] = ((uint32_t)kk * 32u) ^ bXsw;

    // E ldsm lane addressing
    const int eRow = warp * 32 + (lane & 15);
    const uint32_t eOff = (uint32_t)eRow * 128u
                        + ((uint32_t)(((lane >> 4) & 1) * 16) ^ ((uint32_t)((eRow & 7) << 4) & 16u));
    const uint32_t eXsw = (uint32_t)((eRow & 7) << 4) & 0x60u;
    uint32_t kkE[4];
    #pragma unroll
    for (int kk = 0; kk < 4; kk++) kkE[kk] = ((uint32_t)kk * 32u) ^ eXsw;

    int myAct[SEQ];
    {
        const int* ap = acts + (base + tid) * SEQ;
        #pragma unroll
        for (int s = 0; s < SEQ; s++) myAct[s] = ap[s];
    }

    const uint32_t eDstX = (uint32_t)tid * 128u;
    const uint32_t eXor  = (uint32_t)(tid & 7) << 4;
    auto issueE = [&](int s, uint32_t buf) {
        const char* src = reinterpret_cast<const char*>(d_E + (s * 301 + myAct[s]) * DM);
        #pragma unroll
        for (int j = 0; j < 8; j++)
            cpasync16(buf + eDstX + (((uint32_t)j * 16u) ^ eXor), src + j * 16);
    };

    // G1: E0
    issueE(0, sEb[0]); CP_COMMIT();
    // G2: all Ww tiles + epilogue bias
    {
        const char* wsrc = reinterpret_cast<const char*>(d_wwPack);
        #pragma unroll
        for (int it = 0; it < 8; it++) {
            int e = it * THREADS + tid;
            cpasync16(sW + (uint32_t)e * 16u, wsrc + e * 16);
        }
        if (tid < 320) cpasync4(sbase + 196608u + (uint32_t)tid * 4u, d_obPack + tid);
    }
    CP_COMMIT();
    // G3: E1
    issueE(1, sEb[1]); CP_COMMIT();

    unsigned aH[4][8];

    // ---------------- step 0: H = sigmoid(E0) ----------------
    CP_WAITG(2);
    __syncwarp();
    #pragma unroll
    for (int kk = 0; kk < 4; kk++) {
        unsigned e0, e1, e2, e3, e4, e5, e6, e7;
        ldsm4(e0, e1, e2, e3, sEb[0] + eOff + kkE[kk]);
        ldsm4(e4, e5, e6, e7, sEb[0] + eOff + kkE[kk] + 2048u);
        aH[kk][0] = sigpack0(e0); aH[kk][1] = sigpack0(e1);
        aH[kk][2] = sigpack0(e2); aH[kk][3] = sigpack0(e3);
        aH[kk][4] = sigpack0(e4); aH[kk][5] = sigpack0(e5);
        aH[kk][6] = sigpack0(e6); aH[kk][7] = sigpack0(e7);
    }

    // ---------------- steps 1..8: H = sigmoid(E_s + H @ Ww_s^T) ----------------
    #pragma unroll 1
    for (int s = 1; s < SEQ; s++) {
        CP_WAITG(0);
        if (s == 1) __syncthreads();   // publish resident weights (once)
        else        __syncwarp();
        if (s < 8) { issueE(s + 1, sEb[(s + 1) & 1]); CP_COMMIT(); }

        float c0[8][4], c1[8][4];
        #pragma unroll
        for (int nn = 0; nn < 8; nn++) {
            c0[nn][0] = c0[nn][1] = c0[nn][2] = c0[nn][3] = 0.0f;
            c1[nn][0] = c1[nn][1] = c1[nn][2] = c1[nn][3] = 0.0f;
        }
        const uint32_t tb = sW + (uint32_t)(s - 1) * 8192u;
        #pragma unroll
        for (int kk = 0; kk < 4; kk++) {
            #pragma unroll
            for (int np = 0; np < 4; np++) {
                unsigned b0, b1, b2, b3;
                ldsm4(b0, b1, b2, b3, tb + (uint32_t)np * 2048u + bOff + kkB[kk]);
                mma16(c0[2 * np],     aH[kk][0], aH[kk][1], aH[kk][2], aH[kk][3], b0, b1);
                mma16(c1[2 * np],     aH[kk][4], aH[kk][5], aH[kk][6], aH[kk][7], b0, b1);
                mma16(c0[2 * np + 1], aH[kk][0], aH[kk][1], aH[kk][2], aH[kk][3], b2, b3);
                mma16(c1[2 * np + 1], aH[kk][4], aH[kk][5], aH[kk][6], aH[kk][7], b2, b3);
            }
        }
        const uint32_t eb = sEb[s & 1];
        #pragma unroll
        for (int kk = 0; kk < 4; kk++) {
            unsigned e0, e1, e2, e3, e4, e5, e6, e7;
            ldsm4(e0, e1, e2, e3, eb + eOff + kkE[kk]);
            ldsm4(e4, e5, e6, e7, eb + eOff + kkE[kk] + 2048u);
            aH[kk][0] = sigpack2(e0, c0[2 * kk][0],     c0[2 * kk][1]);
            aH[kk][1] = sigpack2(e1, c0[2 * kk][2],     c0[2 * kk][3]);
            aH[kk][2] = sigpack2(e2, c0[2 * kk + 1][0], c0[2 * kk + 1][1]);
            aH[kk][3] = sigpack2(e3, c0[2 * kk + 1][2], c0[2 * kk + 1][3]);
            aH[kk][4] = sigpack2(e4, c1[2 * kk][0],     c1[2 * kk][1]);
            aH[kk][5] = sigpack2(e5, c1[2 * kk][2],     c1[2 * kk][3]);
            aH[kk][6] = sigpack2(e6, c1[2 * kk + 1][0], c1[2 * kk + 1][1]);
            aH[kk][7] = sigpack2(e7, c1[2 * kk + 1][2], c1[2 * kk + 1][3]);
        }
    }

    // ---------------- epilogue: out = H @ out_w^T + out_b ----------------
    __syncthreads();   // all warps done reading sE0 before ow reuse
    {   // ow chunk 0 -> slot 0 (reuses sE0 space)
        const char* osrc = reinterpret_cast<const char*>(d_owPack);
        cpasync16(sEb[0] + (uint32_t)tid * 16u, osrc + tid * 16);
        CP_COMMIT();
    }
    #pragma unroll 1
    for (int nc = 0; nc < 5; nc++) {
        CP_WAITG(0);
        __syncthreads();
        if (nc < 4) {
            const char* osrc = reinterpret_cast<const char*>(d_owPack + (nc + 1) * 4096);
            cpasync16(sEb[0] + (uint32_t)((nc + 1) & 1) * 8192u + (uint32_t)tid * 16u,
                      osrc + tid * 16);
            CP_COMMIT();
        }
        float c0[8][4], c1[8][4];
        #pragma unroll
        for (int nn = 0; nn < 8; nn++) {
            c0[nn][0] = c0[nn][1] = c0[nn][2] = c0[nn][3] = 0.0f;
            c1[nn][0] = c1[nn][1] = c1[nn][2] = c1[nn][3] = 0.0f;
        }
        const uint32_t tb = sEb[0] + (uint32_t)(nc & 1) * 8192u;
        #pragma unroll
        for (int kk = 0; kk < 4; kk++) {
            #pragma unroll
            for (int np = 0; np < 4; np++) {
                unsigned b0, b1, b2, b3;
                ldsm4(b0, b1, b2, b3, tb + (uint32_t)np * 2048u + bOff + kkB[kk]);
                mma16(c0[2 * np],     aH[kk][0], aH[kk][1], aH[kk][2], aH[kk][3], b0, b1);
                mma16(c1[2 * np],     aH[kk][4], aH[kk][5], aH[kk][6], aH[kk][7], b0, b1);
                mma16(c0[2 * np + 1], aH[kk][0], aH[kk][1], aH[kk][2], aH[kk][3], b2, b3);
                mma16(c1[2 * np + 1], aH[kk][4], aH[kk][5], aH[kk][6], aH[kk][7], b2, b3);
            }
        }
        #pragma unroll
        for (int nn = 0; nn < 8; nn++) {
            const int c  = nn * 8 + 2 * tg;
            const int gc = nc * DM + c;
            if (gc < NOUT) {   // pair-uniform (NOUT even), 8B aligned
                const float bb0 = biasEp[gc], bb1 = biasEp[gc + 1];
                float2 p;
                p.x = c0[nn][0] + bb0; p.y = c0[nn][1] + bb1;
                *reinterpret_cast<float2*>(out + (base + rA) * NOUT + gc) = p;
                p.x = c0[nn][2] + bb0; p.y = c0[nn][3] + bb1;
                *reinterpret_cast<float2*>(out + (base + rB) * NOUT + gc) = p;
                p.x = c1[nn][0] + bb0; p.y = c1[nn][1] + bb1;
                *reinterpret_cast<float2*>(out + (base + rC) * NOUT + gc) = p;
                p.x = c1[nn][2] + bb0; p.y = c1[nn][3] + bb1;
                *reinterpret_cast<float2*>(out + (base + rD) * NOUT + gc) = p;
            }
        }
    }
}

extern "C" void kernel_launch(void* const* d_in, const int* in_sizes, int n_in,
                              void* d_out, int out_size) {
    const int*   acts = (const int*)  d_in[0];
    const float* emb  = (const float*)d_in[1];
    const float* Mw   = (const float*)d_in[2];
    const float* Mb   = (const float*)d_in[3];
    const float* Ww   = (const float*)d_in[4];
    const float* Wb   = (const float*)d_in[5];
    const float* outw = (const float*)d_in[6];
    const float* outb = (const float*)d_in[7];
    float* out = (float*)d_out;

    prep_E<<<SEQ * 301, DM>>>(emb, Mw, Mb, Wb);
    const int NP = 8 * 4096 + 5 * 4096 + 320;
    prep_pack<<<(NP + 255) / 256, 256>>>(Ww, outw, outb);

    const int smem = 197888;
    cudaFuncSetAttribute(carnn_kernel, cudaFuncAttributeMaxDynamicSharedMemorySize, smem);
    const int B = in_sizes[0] / SEQ;   // 65536
    carnn_kernel<<<B / ROWS, THREADS, smem>>>(acts, out);
}

// round 17
// speedup vs baseline: 2.7544x; 1.1966x over previous
#include <cuda_runtime.h>
#include <cuda_fp16.h>
#include <cstdint>

#define THREADS 512
#define ROWS    512
#define DM      64
#define SEQ     9
#define NOUT    300

// ---------------- packed parameter store ----------------
__device__ __half d_E[SEQ * 301 * DM];   // E[s][a][c] = emb[a].Mw[s][c] + Mb + Wb
__device__ __half d_wwPack[8 * 4096];    // Ww s=1..8, SW128-swizzled [64n x 64k]
__device__ __half d_owPack[5 * 4096];    // out_w 5 chunks, swizzled, zero-padded
__device__ float  d_obPack[320];         // out_b padded

// Fused prep: blocks 0..44 build E (tiled GEMM); blocks 45.. pack weights.
#define EPREP_BLOCKS 45
#define NPACK (8 * 4096 + 5 * 4096 + 320)

__global__ void prep_all(const float* __restrict__ emb,
                         const float* __restrict__ Mw, const float* __restrict__ Mb,
                         const float* __restrict__ Ww, const float* __restrict__ Wb,
                         const float* __restrict__ outw, const float* __restrict__ outb) {
    if (blockIdx.x < EPREP_BLOCKS) {
        __shared__ float sE[64 * 68], sM[64 * 68];
        const int s = blockIdx.x / 5, a0 = (blockIdx.x % 5) * 64;
        const int tid = threadIdx.x;
        const float4* msrc = reinterpret_cast<const float4*>(Mw + s * 4096);
        #pragma unroll
        for (int it = 0; it < 4; it++) {
            int fi = it * 256 + tid, row = fi >> 4, c4 = fi & 15;
            *reinterpret_cast<float4*>(sM + row * 68 + c4 * 4) = msrc[fi];
        }
        #pragma unroll
        for (int it = 0; it < 4; it++) {
            int fi = it * 256 + tid, row = fi >> 4, c4 = fi & 15;
            int a = a0 + row;
            float4 v = make_float4(0.f, 0.f, 0.f, 0.f);
            if (a < 301) v = *reinterpret_cast<const float4*>(emb + a * DM + c4 * 4);
            *reinterpret_cast<float4*>(sE + row * 68 + c4 * 4) = v;
        }
        __syncthreads();
        const int ci = tid & 15, aj = tid >> 4;   // c = ci+16*jc, a = a0+aj+16*ja
        float acc[4][4];
        #pragma unroll
        for (int jc = 0; jc < 4; jc++) {
            int c = ci + 16 * jc;
            float b = Mb[s * DM + c] + Wb[s * DM + c];
            #pragma unroll
            for (int ja = 0; ja < 4; ja++) acc[ja][jc] = b;
        }
        #pragma unroll
        for (int k4 = 0; k4 < 16; k4++) {
            float4 ev[4], mv[4];
            #pragma unroll
            for (int ja = 0; ja < 4; ja++)
                ev[ja] = *reinterpret_cast<const float4*>(sE + (aj + 16 * ja) * 68 + k4 * 4);
            #pragma unroll
            for (int jc = 0; jc < 4; jc++)
                mv[jc] = *reinterpret_cast<const float4*>(sM + (ci + 16 * jc) * 68 + k4 * 4);
            #pragma unroll
            for (int ja = 0; ja < 4; ja++)
                #pragma unroll
                for (int jc = 0; jc < 4; jc++)
                    acc[ja][jc] += ev[ja].x * mv[jc].x + ev[ja].y * mv[jc].y
                                 + ev[ja].z * mv[jc].z + ev[ja].w * mv[jc].w;
        }
        #pragma unroll
        for (int ja = 0; ja < 4; ja++) {
            int a = a0 + aj + 16 * ja;
            if (a < 301) {
                #pragma unroll
                for (int jc = 0; jc < 4; jc++)
                    d_E[(s * 301 + a) * DM + ci + 16 * jc] = __float2half(acc[ja][jc]);
            }
        }
        return;
    }
    // ---- packing part ----
    const int N1 = 8 * 4096, N2 = 5 * 4096;
    int i = (blockIdx.x - EPREP_BLOCKS) * blockDim.x + threadIdx.x;
    if (i < N1) {
        int t = i >> 12, r = i & 4095, n = r >> 6, k = r & 63;
        float v = Ww[(t + 1) * 4096 + n * DM + k];
        uint32_t sw = (uint32_t)n * 128u + (((uint32_t)k * 2u) ^ (((uint32_t)(n & 7)) << 4));
        d_wwPack[t * 4096 + (sw >> 1)] = __float2half(v);
        return;
    }
    int j = i - N1;
    if (j < N2) {
        int nc = j >> 12, r = j & 4095, n = r >> 6, k = r & 63;
        int gn = nc * DM + n;
        float v = (gn < NOUT) ? outw[gn * DM + k] : 0.0f;
        uint32_t sw = (uint32_t)n * 128u + (((uint32_t)k * 2u) ^ (((uint32_t)(n & 7)) << 4));
        d_owPack[nc * 4096 + (sw >> 1)] = __float2half(v);
        return;
    }
    int p = j - N2;
    if (p < 320) d_obPack[p] = (p < NOUT) ? outb[p] : 0.0f;
}

// ---------------- device helpers ----------------
__device__ __forceinline__ uint32_t smem_u32(const void* p) {
    uint32_t a;
    asm("{ .reg .u64 t; cvta.to.shared.u64 t, %1; cvt.u32.u64 %0, t; }" : "=r"(a) : "l"(p));
    return a;
}
__device__ __forceinline__ unsigned pack2(float a, float b) {
    __half2 h = __floats2half2_rn(a, b);
    return *reinterpret_cast<unsigned*>(&h);
}
__device__ __forceinline__ float sigf(float v) {
    float t;
    asm("tanh.approx.f32 %0, %1;" : "=f"(t) : "f"(v * 0.5f));
    return fmaf(0.5f, t, 0.5f);
}
__device__ __forceinline__ unsigned sigpack0(unsigned eh) {
    float2 e = __half22float2(*reinterpret_cast<__half2*>(&eh));
    return pack2(sigf(e.x), sigf(e.y));
}
__device__ __forceinline__ unsigned sigpack2(unsigned eh, float a0, float a1) {
    float2 e = __half22float2(*reinterpret_cast<__half2*>(&eh));
    return pack2(sigf(e.x + a0), sigf(e.y + a1));
}
__device__ __forceinline__ void cpasync16(uint32_t dst, const void* src) {
    asm volatile("cp.async.cg.shared.global [%0], [%1], 16;" :: "r"(dst), "l"(src));
}
__device__ __forceinline__ void cpasync4(uint32_t dst, const void* src) {
    asm volatile("cp.async.ca.shared.global [%0], [%1], 4;" :: "r"(dst), "l"(src));
}
#define CP_COMMIT() asm volatile("cp.async.commit_group;" ::: "memory")
#define CP_WAITG(n) asm volatile("cp.async.wait_group %0;" :: "n"(n) : "memory")

__device__ __forceinline__ void ldsm4(unsigned& r0, unsigned& r1, unsigned& r2, unsigned& r3,
                                      uint32_t addr) {
    asm volatile("ldmatrix.sync.aligned.m8n8.x4.shared.b16 {%0,%1,%2,%3}, [%4];"
                 : "=r"(r0), "=r"(r1), "=r"(r2), "=r"(r3) : "r"(addr));
}
__device__ __forceinline__ void mma16(float* c,
                                      unsigned a0, unsigned a1, unsigned a2, unsigned a3,
                                      unsigned b0, unsigned b1) {
    asm volatile(
        "mma.sync.aligned.m16n8k16.row.col.f32.f16.f16.f32 "
        "{%0,%1,%2,%3}, {%4,%5,%6,%7}, {%8,%9}, {%0,%1,%2,%3};"
        : "+f"(c[0]), "+f"(c[1]), "+f"(c[2]), "+f"(c[3])
        : "r"(a0), "r"(a1), "r"(a2), "r"(a3), "r"(b0), "r"(b1));
}

// ---------------- main kernel ----------------
// SMEM: [0]      sW: 8 x 8192   (Ww tiles, steps 1..8)
//       [65536]  sE0: 512 x 128 (E buffer parity 0; E8 lives here at s=8)
//       [131072] sE1: 512 x 128 (E buffer parity 1; epilogue: 5 ow tiles)
//       [196608] biasEp: 320 f32        total 197888 B -> 1 CTA/SM
__global__ void __launch_bounds__(THREADS) carnn_kernel(
    const int* __restrict__ acts, float* __restrict__ out)
{
    extern __shared__ __align__(128) char smem[];
    const uint32_t sbase = smem_u32(smem);
    const uint32_t sW = sbase;
    const uint32_t sEb[2] = { sbase + 65536u, sbase + 131072u };
    float* biasEp = reinterpret_cast<float*>(smem + 196608);

    const int tid = threadIdx.x, lane = tid & 31, warp = tid >> 5;
    const int g = lane >> 2, tg = lane & 3;
    const int rA = warp * 32 + g, rB = rA + 8, rC = rA + 16, rD = rA + 24;
    const long base = (long)blockIdx.x * ROWS;

    // B ldsm lane addressing (swizzled 128B rows)
    const int nb = (lane & 7) + ((lane & 16) >> 1);
    const uint32_t bOff = (uint32_t)nb * 128u
                        + ((uint32_t)((lane & 8) << 1) ^ ((uint32_t)((nb & 7) << 4) & 16u));
    const uint32_t bXsw = (uint32_t)((nb & 7) << 4) & 0x60u;
    uint32_t kkB[4];
    #pragma unroll
    for (int kk = 0; kk < 4; kk++) kkB[kk] = ((uint32_t)kk * 32u) ^ bXsw;

    // E ldsm lane addressing
    const int eRow = warp * 32 + (lane & 15);
    const uint32_t eOff = (uint32_t)eRow * 128u
                        + ((uint32_t)(((lane >> 4) & 1) * 16) ^ ((uint32_t)((eRow & 7) << 4) & 16u));
    const uint32_t eXsw = (uint32_t)((eRow & 7) << 4) & 0x60u;
    uint32_t kkE[4];
    #pragma unroll
    for (int kk = 0; kk < 4; kk++) kkE[kk] = ((uint32_t)kk * 32u) ^ eXsw;

    int myAct[SEQ];
    {
        const int* ap = acts + (base + tid) * SEQ;
        #pragma unroll
        for (int s = 0; s < SEQ; s++) myAct[s] = ap[s];
    }

    const uint32_t eDstX = (uint32_t)tid * 128u;
    const uint32_t eXor  = (uint32_t)(tid & 7) << 4;
    auto issueE = [&](int s, uint32_t buf) {
        const char* src = reinterpret_cast<const char*>(d_E + (s * 301 + myAct[s]) * DM);
        #pragma unroll
        for (int j = 0; j < 8; j++)
            cpasync16(buf + eDstX + (((uint32_t)j * 16u) ^ eXor), src + j * 16);
    };

    // G1: E0
    issueE(0, sEb[0]); CP_COMMIT();
    // G2: all Ww tiles + epilogue bias
    {
        const char* wsrc = reinterpret_cast<const char*>(d_wwPack);
        #pragma unroll
        for (int it = 0; it < 8; it++) {
            int e = it * THREADS + tid;
            cpasync16(sW + (uint32_t)e * 16u, wsrc + e * 16);
        }
        if (tid < 320) cpasync4(sbase + 196608u + (uint32_t)tid * 4u, d_obPack + tid);
    }
    CP_COMMIT();
    // G3: E1
    issueE(1, sEb[1]); CP_COMMIT();

    unsigned aH[4][8];

    // ---------------- step 0: H = sigmoid(E0) ----------------
    CP_WAITG(2);
    __syncwarp();
    #pragma unroll
    for (int kk = 0; kk < 4; kk++) {
        unsigned e0, e1, e2, e3, e4, e5, e6, e7;
        ldsm4(e0, e1, e2, e3, sEb[0] + eOff + kkE[kk]);
        ldsm4(e4, e5, e6, e7, sEb[0] + eOff + kkE[kk] + 2048u);
        aH[kk][0] = sigpack0(e0); aH[kk][1] = sigpack0(e1);
        aH[kk][2] = sigpack0(e2); aH[kk][3] = sigpack0(e3);
        aH[kk][4] = sigpack0(e4); aH[kk][5] = sigpack0(e5);
        aH[kk][6] = sigpack0(e6); aH[kk][7] = sigpack0(e7);
    }

    // ---------------- steps 1..8: H = sigmoid(E_s + H @ Ww_s^T) ----------------
    #pragma unroll 1
    for (int s = 1; s < SEQ; s++) {
        CP_WAITG(0);
        if (s == 1 || s == 8) __syncthreads();  // s=1: publish weights; s=8: sE1 free for ow
        else                  __syncwarp();
        if (s < 8) { issueE(s + 1, sEb[(s + 1) & 1]); CP_COMMIT(); }
        else {
            // preload ALL 5 out_w tiles into sE1 (E7 fully consumed; barrier above)
            const char* osrc = reinterpret_cast<const char*>(d_owPack);
            #pragma unroll
            for (int nc = 0; nc < 5; nc++)
                cpasync16(sEb[1] + (uint32_t)nc * 8192u + (uint32_t)tid * 16u,
                          osrc + nc * 8192 + tid * 16);
            CP_COMMIT();
        }

        float c0[8][4], c1[8][4];
        #pragma unroll
        for (int nn = 0; nn < 8; nn++) {
            c0[nn][0] = c0[nn][1] = c0[nn][2] = c0[nn][3] = 0.0f;
            c1[nn][0] = c1[nn][1] = c1[nn][2] = c1[nn][3] = 0.0f;
        }
        const uint32_t tb = sW + (uint32_t)(s - 1) * 8192u;
        #pragma unroll
        for (int kk = 0; kk < 4; kk++) {
            #pragma unroll
            for (int np = 0; np < 4; np++) {
                unsigned b0, b1, b2, b3;
                ldsm4(b0, b1, b2, b3, tb + (uint32_t)np * 2048u + bOff + kkB[kk]);
                mma16(c0[2 * np],     aH[kk][0], aH[kk][1], aH[kk][2], aH[kk][3], b0, b1);
                mma16(c1[2 * np],     aH[kk][4], aH[kk][5], aH[kk][6], aH[kk][7], b0, b1);
                mma16(c0[2 * np + 1], aH[kk][0], aH[kk][1], aH[kk][2], aH[kk][3], b2, b3);
                mma16(c1[2 * np + 1], aH[kk][4], aH[kk][5], aH[kk][6], aH[kk][7], b2, b3);
            }
        }
        const uint32_t eb = sEb[s & 1];
        #pragma unroll
        for (int kk = 0; kk < 4; kk++) {
            unsigned e0, e1, e2, e3, e4, e5, e6, e7;
            ldsm4(e0, e1, e2, e3, eb + eOff + kkE[kk]);
            ldsm4(e4, e5, e6, e7, eb + eOff + kkE[kk] + 2048u);
            aH[kk][0] = sigpack2(e0, c0[2 * kk][0],     c0[2 * kk][1]);
            aH[kk][1] = sigpack2(e1, c0[2 * kk][2],     c0[2 * kk][3]);
            aH[kk][2] = sigpack2(e2, c0[2 * kk + 1][0], c0[2 * kk + 1][1]);
            aH[kk][3] = sigpack2(e3, c0[2 * kk + 1][2], c0[2 * kk + 1][3]);
            aH[kk][4] = sigpack2(e4, c1[2 * kk][0],     c1[2 * kk][1]);
            aH[kk][5] = sigpack2(e5, c1[2 * kk][2],     c1[2 * kk][3]);
            aH[kk][6] = sigpack2(e6, c1[2 * kk + 1][0], c1[2 * kk + 1][1]);
            aH[kk][7] = sigpack2(e7, c1[2 * kk + 1][2], c1[2 * kk + 1][3]);
        }
    }

    // ---------------- epilogue: out = H @ out_w^T + out_b (no per-chunk syncs) ----------------
    CP_WAITG(0);
    __syncthreads();   // publish all 5 ow tiles
    #pragma unroll 1
    for (int nc = 0; nc < 5; nc++) {
        float c0[8][4], c1[8][4];
        #pragma unroll
        for (int nn = 0; nn < 8; nn++) {
            c0[nn][0] = c0[nn][1] = c0[nn][2] = c0[nn][3] = 0.0f;
            c1[nn][0] = c1[nn][1] = c1[nn][2] = c1[nn][3] = 0.0f;
        }
        const uint32_t tb = sEb[1] + (uint32_t)nc * 8192u;
        #pragma unroll
        for (int kk = 0; kk < 4; kk++) {
            #pragma unroll
            for (int np = 0; np < 4; np++) {
                unsigned b0, b1, b2, b3;
                ldsm4(b0, b1, b2, b3, tb + (uint32_t)np * 2048u + bOff + kkB[kk]);
                mma16(c0[2 * np],     aH[kk][0], aH[kk][1], aH[kk][2], aH[kk][3], b0, b1);
                mma16(c1[2 * np],     aH[kk][4], aH[kk][5], aH[kk][6], aH[kk][7], b0, b1);
                mma16(c0[2 * np + 1], aH[kk][0], aH[kk][1], aH[kk][2], aH[kk][3], b2, b3);
                mma16(c1[2 * np + 1], aH[kk][4], aH[kk][5], aH[kk][6], aH[kk][7], b2, b3);
            }
        }
        #pragma unroll
        for (int nn = 0; nn < 8; nn++) {
            const int c  = nn * 8 + 2 * tg;
            const int gc = nc * DM + c;
            if (gc < NOUT) {   // pair-uniform (NOUT even), 8B aligned
                const float bb0 = biasEp[gc], bb1 = biasEp[gc + 1];
                float2 p;
                p.x = c0[nn][0] + bb0; p.y = c0[nn][1] + bb1;
                *reinterpret_cast<float2*>(out + (base + rA) * NOUT + gc) = p;
                p.x = c0[nn][2] + bb0; p.y = c0[nn][3] + bb1;
                *reinterpret_cast<float2*>(out + (base + rB) * NOUT + gc) = p;
                p.x = c1[nn][0] + bb0; p.y = c1[nn][1] + bb1;
                *reinterpret_cast<float2*>(out + (base + rC) * NOUT + gc) = p;
                p.x = c1[nn][2] + bb0; p.y = c1[nn][3] + bb1;
                *reinterpret_cast<float2*>(out + (base + rD) * NOUT + gc) = p;
            }
        }
    }
}

extern "C" void kernel_launch(void* const* d_in, const int* in_sizes, int n_in,
                              void* d_out, int out_size) {
    const int*   acts = (const int*)  d_in[0];
    const float* emb  = (const float*)d_in[1];
    const float* Mw   = (const float*)d_in[2];
    const float* Mb   = (const float*)d_in[3];
    const float* Ww   = (const float*)d_in[4];
    const float* Wb   = (const float*)d_in[5];
    const float* outw = (const float*)d_in[6];
    const float* outb = (const float*)d_in[7];
    float* out = (float*)d_out;

    const int packBlocks = (NPACK + 255) / 256;
    prep_all<<<EPREP_BLOCKS + packBlocks, 256>>>(emb, Mw, Mb, Ww, Wb, outw, outb);

    const int smem = 197888;
    cudaFuncSetAttribute(carnn_kernel, cudaFuncAttributeMaxDynamicSharedMemorySize, smem);
    const int B = in_sizes[0] / SEQ;   // 65536
    carnn_kernel<<<B / ROWS, THREADS, smem>>>(acts, out);
}